// round 6
// baseline (speedup 1.0000x reference)
#include <cuda_runtime.h>
#include <cuda_bf16.h>
#include <cuda_fp8.h>
#include <cstdint>
#include <math.h>

#define T 2048
#define D 1024
#define H 16
#define DH 64
#define NC 16
#define CS 128
#define GK 1024
#define LO_SCALE 4096.0f
#define INV_LO_SCALE (1.0f/4096.0f)

// ---------------- scratch (no allocations allowed) ----------------
__device__ float g_gate[T*D];
__device__ float g_qkv[T*3*D];
__device__ float g_Q[T*D];
__device__ float g_K[T*D];
__device__ float g_V[T*D];
__device__ float g_lkv[H*NC*DH*DH];
__device__ float g_lks[H*NC*DH];
__device__ float g_Spre[H*NC*DH*DH];
__device__ float g_zpre[H*NC*DH];

// bf16 hi + fp8 (full, scaled-lo) forms
__device__ __nv_bfloat16 g_xh[T*D];
__device__ uint8_t       g_x8[T*D],  g_xl8[T*D];
__device__ __nv_bfloat16 g_xnh[T*D];
__device__ uint8_t       g_xn8[T*D], g_xnl8[T*D];
__device__ __nv_bfloat16 g_ah[T*D];
__device__ uint8_t       g_a8[T*D],  g_al8[T*D];
__device__ __nv_bfloat16 g_qwh[3*D*D];
__device__ uint8_t       g_qw8[3*D*D], g_qwl8[3*D*D];
__device__ __nv_bfloat16 g_gwh[D*D];
__device__ uint8_t       g_gw8[D*D], g_gwl8[D*D];
__device__ __nv_bfloat16 g_pwh[D*D];
__device__ uint8_t       g_pw8[D*D], g_pwl8[D*D];

// ---------------- helpers ----------------
__device__ __forceinline__ uint32_t smem_u32(const void* p){
  uint32_t a;
  asm("{ .reg .u64 t; cvta.to.shared.u64 t, %1; cvt.u32.u64 %0, t; }" : "=r"(a) : "l"(p));
  return a;
}
__device__ __forceinline__ float elu1f(float x){ return x > 0.f ? x + 1.f : expf(x); }

__device__ __forceinline__ uint32_t pack4_e4m3(float a, float b, float c, float d){
  __nv_fp8x2_storage_t lo = __nv_cvt_float2_to_fp8x2(make_float2(a,b), __NV_SATFINITE, __NV_E4M3);
  __nv_fp8x2_storage_t hi = __nv_cvt_float2_to_fp8x2(make_float2(c,d), __NV_SATFINITE, __NV_E4M3);
  return (uint32_t)lo | ((uint32_t)hi << 16);
}

// emit hi(bf16 x4), full fp8 x4, scaled-lo fp8 x4 for 4 consecutive floats
__device__ __forceinline__ void emit_split4(const float* v,
    __nv_bfloat16* hp, uint32_t* f8p, uint32_t* l8p, size_t idx4)
{
  __nv_bfloat16 hv[4]; float lv[4];
  #pragma unroll
  for (int k = 0; k < 4; k++){
    hv[k] = __float2bfloat16(v[k]);
    lv[k] = (v[k] - __bfloat162float(hv[k])) * LO_SCALE;
  }
  ((__nv_bfloat162*)hp)[idx4*2]   = __nv_bfloat162(hv[0], hv[1]);
  ((__nv_bfloat162*)hp)[idx4*2+1] = __nv_bfloat162(hv[2], hv[3]);
  f8p[idx4] = pack4_e4m3(v[0], v[1], v[2], v[3]);
  l8p[idx4] = pack4_e4m3(lv[0], lv[1], lv[2], lv[3]);
}

__device__ __forceinline__ void ldsm_x4(uint32_t* r, uint32_t addr){
  asm volatile("ldmatrix.sync.aligned.m8n8.x4.shared.b16 {%0,%1,%2,%3}, [%4];"
    : "=r"(r[0]), "=r"(r[1]), "=r"(r[2]), "=r"(r[3]) : "r"(addr));
}
__device__ __forceinline__ void mma_bf16(float* c, const uint32_t* a, const uint32_t* b){
  asm volatile(
    "mma.sync.aligned.m16n8k16.row.col.f32.bf16.bf16.f32 "
    "{%0,%1,%2,%3},{%4,%5,%6,%7},{%8,%9},{%0,%1,%2,%3};"
    : "+f"(c[0]), "+f"(c[1]), "+f"(c[2]), "+f"(c[3])
    : "r"(a[0]), "r"(a[1]), "r"(a[2]), "r"(a[3]), "r"(b[0]), "r"(b[1]));
}
__device__ __forceinline__ void mma_fp8(float* c, const uint32_t* a, const uint32_t* b){
  asm volatile(
    "mma.sync.aligned.m16n8k32.row.col.f32.e4m3.e4m3.f32 "
    "{%0,%1,%2,%3},{%4,%5,%6,%7},{%8,%9},{%0,%1,%2,%3};"
    : "+f"(c[0]), "+f"(c[1]), "+f"(c[2]), "+f"(c[3])
    : "r"(a[0]), "r"(a[1]), "r"(a[2]), "r"(a[3]), "r"(b[0]), "r"(b[1]));
}
__device__ __forceinline__ void cp16(uint32_t smem, const void* gmem){
  asm volatile("cp.async.cg.shared.global [%0], [%1], 16;" :: "r"(smem), "l"(gmem));
}
__device__ __forceinline__ void cp_commit(){
  asm volatile("cp.async.commit_group;" ::: "memory");
}
template<int N>
__device__ __forceinline__ void cp_wait(){
  asm volatile("cp.async.wait_group %0;" :: "n"(N) : "memory");
}

// ---------------- fused split fp32 -> (bf16 hi, fp8, fp8 lo) ----------------
#define X4 (T*D/4)
#define Q4 (3*D*D/4)
#define G4 (D*D/4)
#define P4 (D*D/4)
__global__ void split_all_kernel(const float* __restrict__ x, const float* __restrict__ qw,
                                 const float* __restrict__ gw, const float* __restrict__ pw)
{
  int i = blockIdx.x * 256 + threadIdx.x;
  const float* src; __nv_bfloat16* hp; uint32_t *f8p, *l8p; int j;
  if (i < X4){ src = x; hp = g_xh; f8p = (uint32_t*)g_x8; l8p = (uint32_t*)g_xl8; j = i; }
  else if (i < X4 + Q4){ src = qw; hp = g_qwh; f8p = (uint32_t*)g_qw8; l8p = (uint32_t*)g_qwl8; j = i - X4; }
  else if (i < X4 + Q4 + G4){ src = gw; hp = g_gwh; f8p = (uint32_t*)g_gw8; l8p = (uint32_t*)g_gwl8; j = i - (X4 + Q4); }
  else { src = pw; hp = g_pwh; f8p = (uint32_t*)g_pw8; l8p = (uint32_t*)g_pwl8; j = i - (X4 + Q4 + G4); }
  float4 v4 = ((const float4*)src)[j];
  float v[4] = {v4.x, v4.y, v4.z, v4.w};
  emit_split4(v, hp, f8p, l8p, j);
}

// ---------------- LayerNorm -> bf16 hi + fp8 forms ----------------
__global__ void ln_kernel(const float* __restrict__ x, const float* __restrict__ g,
                          const float* __restrict__ b)
{
  __shared__ float red[16];
  const int t = blockIdx.x;
  const int i = threadIdx.x;
  float4 xv = ((const float4*)(x + (size_t)t*D))[i];
  float s  = xv.x + xv.y + xv.z + xv.w;
  float s2 = xv.x*xv.x + xv.y*xv.y + xv.z*xv.z + xv.w*xv.w;
  const int lane = i & 31, w = i >> 5;
  #pragma unroll
  for (int o = 16; o; o >>= 1){
    s  += __shfl_xor_sync(0xffffffffu, s,  o);
    s2 += __shfl_xor_sync(0xffffffffu, s2, o);
  }
  if (lane == 0){ red[w] = s; red[8+w] = s2; }
  __syncthreads();
  if (i == 0){
    float a = 0.f, c = 0.f;
    #pragma unroll
    for (int k = 0; k < 8; k++){ a += red[k]; c += red[8+k]; }
    red[0] = a; red[8] = c;
  }
  __syncthreads();
  const float mu   = red[0] * (1.f / D);
  const float var  = red[8] * (1.f / D) - mu * mu;
  const float rstd = rsqrtf(var + 1e-5f);
  float4 gv = ((const float4*)g)[i];
  float4 bv = ((const float4*)b)[i];
  float o[4];
  o[0] = (xv.x - mu) * rstd * gv.x + bv.x;
  o[1] = (xv.y - mu) * rstd * gv.y + bv.y;
  o[2] = (xv.z - mu) * rstd * gv.z + bv.z;
  o[3] = (xv.w - mu) * rstd * gv.w + bv.w;
  const size_t idx4 = ((size_t)t*D >> 2) + i;
  emit_split4(o, g_xnh, (uint32_t*)g_xn8, (uint32_t*)g_xnl8, idx4);
}

// ---------------- HMMA+QMMA GEMM: C[2048,N] = A[2048,1024] @ B[N,1024]^T ----------------
// main:  Ah(bf16) Bh(bf16)  -> acc
// corr:  A(fp8)*Blo8 + Alo8*B(fp8) -> accc  (lo pre-scaled by 4096)
// C = acc + accc/4096 + bias
#define PITCH16 80
#define ARR16   (128*PITCH16)  // 10240
#define PITCH8  48
#define ARR8    (128*PITCH8)   // 6144
#define OFF_AH  0
#define OFF_BH  (ARR16)
#define OFF_A8  (2*ARR16)
#define OFF_AL8 (2*ARR16 + ARR8)
#define OFF_B8  (2*ARR16 + 2*ARR8)
#define OFF_BL8 (2*ARR16 + 3*ARR8)
#define STAGE   (2*ARR16 + 4*ARR8) // 45056
#define NRING 4
#define NKT   (GK/32)
#define GEMM_SMEM (NRING*STAGE)    // 180224

struct GArgs {
  const __nv_bfloat16* Ah;
  const uint8_t *A8, *Al8;
  const __nv_bfloat16* Bh;
  const uint8_t *B8, *Bl8;
  const float* bias;
  float* C;
  int N;
  int sig;
};

__device__ __forceinline__ void gemm_load_stage(uint32_t sbase,
    const __nv_bfloat16* Ah, const uint8_t* A8, const uint8_t* Al8,
    const __nv_bfloat16* Bh, const uint8_t* B8, const uint8_t* Bl8,
    int kt, int tid)
{
  const int koff = kt * 32;  // elements for bf16, bytes for fp8
  #pragma unroll
  for (int it = 0; it < 2; it++){
    const int w = tid + it * 256;
    const int row = w >> 2, c = w & 3;
    cp16(sbase + OFF_AH + row*PITCH16 + c*16, Ah + (size_t)row * GK + koff + c*8);
    cp16(sbase + OFF_BH + row*PITCH16 + c*16, Bh + (size_t)row * GK + koff + c*8);
  }
  const int row8 = tid >> 1, c8 = tid & 1;
  cp16(sbase + OFF_A8  + row8*PITCH8 + c8*16, A8  + (size_t)row8 * GK + koff + c8*16);
  cp16(sbase + OFF_AL8 + row8*PITCH8 + c8*16, Al8 + (size_t)row8 * GK + koff + c8*16);
  cp16(sbase + OFF_B8  + row8*PITCH8 + c8*16, B8  + (size_t)row8 * GK + koff + c8*16);
  cp16(sbase + OFF_BL8 + row8*PITCH8 + c8*16, Bl8 + (size_t)row8 * GK + koff + c8*16);
}

__global__ void __launch_bounds__(256, 1)
hmma_gemm_dual(GArgs g0, GArgs g1, int split)
{
  extern __shared__ __align__(128) char sm[];
  const uint32_t sb = smem_u32(sm);
  const int tid = threadIdx.x;
  const int wid = tid >> 5, lane = tid & 31;
  const int wm = wid & 1, wn = wid >> 1;
  const int m0w = wm * 64, n0w = wn * 32;

  const bool first = ((int)blockIdx.x < split);
  const GArgs ga = first ? g0 : g1;
  const int bxn = first ? (int)blockIdx.x : (int)blockIdx.x - split;
  const int bn0 = bxn << 7, bm0 = blockIdx.y << 7;

  const __nv_bfloat16* pAh = ga.Ah + (size_t)bm0 * GK;
  const uint8_t* pA8  = ga.A8  + (size_t)bm0 * GK;
  const uint8_t* pAl8 = ga.Al8 + (size_t)bm0 * GK;
  const __nv_bfloat16* pBh = ga.Bh + (size_t)bn0 * GK;
  const uint8_t* pB8  = ga.B8  + (size_t)bn0 * GK;
  const uint8_t* pBl8 = ga.Bl8 + (size_t)bn0 * GK;

  float acc[4][4][4], accc[4][4][4];
  #pragma unroll
  for (int i = 0; i < 4; i++)
    #pragma unroll
    for (int j = 0; j < 4; j++)
      #pragma unroll
      for (int q = 0; q < 4; q++){ acc[i][j][q] = 0.f; accc[i][j][q] = 0.f; }

  // ldmatrix per-lane offsets (same pattern serves bf16 and fp8 tiles)
  const int rowA = lane & 15;
  const uint32_t colA = (lane >> 4) << 4;                 // 0 or 16 bytes
  const int rowB = (lane & 7) + (((lane >> 4) & 1) << 3); // 0..15
  const uint32_t colB = ((lane >> 3) & 1) << 4;           // 0 or 16 bytes

  gemm_load_stage(sb + 0*STAGE, pAh, pA8, pAl8, pBh, pB8, pBl8, 0, tid); cp_commit();
  gemm_load_stage(sb + 1*STAGE, pAh, pA8, pAl8, pBh, pB8, pBl8, 1, tid); cp_commit();
  gemm_load_stage(sb + 2*STAGE, pAh, pA8, pAl8, pBh, pB8, pBl8, 2, tid); cp_commit();

  for (int kt = 0; kt < NKT; kt++){
    cp_wait<2>();
    __syncthreads();

    if (kt + 3 < NKT)
      gemm_load_stage(sb + ((kt + 3) & (NRING-1)) * STAGE,
                      pAh, pA8, pAl8, pBh, pB8, pBl8, kt + 3, tid);
    cp_commit();

    const uint32_t st = sb + (kt & (NRING-1)) * STAGE;
    const uint32_t aB16 = st + OFF_AH  + (m0w + rowA) * PITCH16 + colA;
    const uint32_t bB16 = st + OFF_BH  + (n0w + rowB) * PITCH16 + colB;
    const uint32_t aB8  = st + OFF_A8  + (m0w + rowA) * PITCH8  + colA;
    const uint32_t alB8 = st + OFF_AL8 + (m0w + rowA) * PITCH8  + colA;
    const uint32_t bB8  = st + OFF_B8  + (n0w + rowB) * PITCH8  + colB;
    const uint32_t blB8 = st + OFF_BL8 + (n0w + rowB) * PITCH8  + colB;

    // main term: bf16, two k16 halves
    #pragma unroll
    for (int ks = 0; ks < 2; ks++){
      const uint32_t kb = ks * 32;
      uint32_t a16[4][4], b16[4][2];
      #pragma unroll
      for (int mi = 0; mi < 4; mi++)
        ldsm_x4(a16[mi], aB16 + mi*16*PITCH16 + kb);
      #pragma unroll
      for (int p = 0; p < 2; p++){
        uint32_t r[4];
        ldsm_x4(r, bB16 + p*16*PITCH16 + kb);
        b16[2*p][0] = r[0]; b16[2*p][1] = r[1];
        b16[2*p+1][0] = r[2]; b16[2*p+1][1] = r[3];
      }
      #pragma unroll
      for (int mi = 0; mi < 4; mi++)
        #pragma unroll
        for (int nj = 0; nj < 4; nj++)
          mma_bf16(acc[mi][nj], a16[mi], b16[nj]);
    }

    // correction terms: fp8, full k32 per MMA
    {
      uint32_t a8f[4][4], al8f[4][4], b8f[4][2], bl8f[4][2];
      #pragma unroll
      for (int mi = 0; mi < 4; mi++){
        ldsm_x4(a8f[mi],  aB8  + mi*16*PITCH8);
        ldsm_x4(al8f[mi], alB8 + mi*16*PITCH8);
      }
      #pragma unroll
      for (int p = 0; p < 2; p++){
        uint32_t r[4];
        ldsm_x4(r, bB8 + p*16*PITCH8);
        b8f[2*p][0] = r[0]; b8f[2*p][1] = r[1];
        b8f[2*p+1][0] = r[2]; b8f[2*p+1][1] = r[3];
        ldsm_x4(r, blB8 + p*16*PITCH8);
        bl8f[2*p][0] = r[0]; bl8f[2*p][1] = r[1];
        bl8f[2*p+1][0] = r[2]; bl8f[2*p+1][1] = r[3];
      }
      #pragma unroll
      for (int mi = 0; mi < 4; mi++)
        #pragma unroll
        for (int nj = 0; nj < 4; nj++){
          mma_fp8(accc[mi][nj], a8f[mi],  bl8f[nj]);
          mma_fp8(accc[mi][nj], al8f[mi], b8f[nj]);
        }
    }
  }

  // epilogue
  const int g = lane >> 2, t4 = lane & 3;
  #pragma unroll
  for (int mi = 0; mi < 4; mi++){
    #pragma unroll
    for (int nj = 0; nj < 4; nj++){
      const int row = bm0 + m0w + mi*16 + g;
      const int col = bn0 + n0w + nj*8 + t4*2;
      float b0 = ga.bias[col], b1 = ga.bias[col+1];
      float o0 = acc[mi][nj][0] + accc[mi][nj][0] * INV_LO_SCALE + b0;
      float o1 = acc[mi][nj][1] + accc[mi][nj][1] * INV_LO_SCALE + b1;
      float o2 = acc[mi][nj][2] + accc[mi][nj][2] * INV_LO_SCALE + b0;
      float o3 = acc[mi][nj][3] + accc[mi][nj][3] * INV_LO_SCALE + b1;
      if (ga.sig){
        o0 = 1.f / (1.f + expf(-o0)); o1 = 1.f / (1.f + expf(-o1));
        o2 = 1.f / (1.f + expf(-o2)); o3 = 1.f / (1.f + expf(-o3));
      }
      *(float2*)(ga.C + (size_t)row * ga.N + col)       = make_float2(o0, o1);
      *(float2*)(ga.C + (size_t)(row + 8) * ga.N + col) = make_float2(o2, o3);
    }
  }
}

// ---------------- gate-normalize + apply + elu+1 + head split ----------------
__global__ void prep_kernel(const float* __restrict__ gate, const float* __restrict__ qkv,
                            float* __restrict__ Q, float* __restrict__ K, float* __restrict__ V)
{
  __shared__ float red[8];
  const int t = blockIdx.x, i = threadIdx.x;
  float4 gv = ((const float4*)(gate + (size_t)t*D))[i];
  float s = gv.x + gv.y + gv.z + gv.w;
  const int lane = i & 31, w = i >> 5;
  #pragma unroll
  for (int o = 16; o; o >>= 1) s += __shfl_xor_sync(0xffffffffu, s, o);
  if (lane == 0) red[w] = s;
  __syncthreads();
  if (i == 0){
    float a = 0.f;
    #pragma unroll
    for (int k = 0; k < 8; k++) a += red[k];
    red[0] = a;
  }
  __syncthreads();
  const float inv = 1.f / (red[0] * (1.f / D) + 1e-5f);

  const float4* qrow = (const float4*)(qkv + (size_t)t * 3 * D);
  float4 qv = qrow[i], kv = qrow[i + 256], vv = qrow[i + 512];
  float4 qo, ko;
  qo.x = elu1f(qv.x * gv.x * inv); qo.y = elu1f(qv.y * gv.y * inv);
  qo.z = elu1f(qv.z * gv.z * inv); qo.w = elu1f(qv.w * gv.w * inv);
  ko.x = elu1f(kv.x * gv.x * inv); ko.y = elu1f(kv.y * gv.y * inv);
  ko.z = elu1f(kv.z * gv.z * inv); ko.w = elu1f(kv.w * gv.w * inv);

  const int h = i >> 4;
  const int dh = (i & 15) << 2;
  const size_t b4 = ((size_t)(h * T + t) * DH + dh) >> 2;
  ((float4*)Q)[b4] = qo;
  ((float4*)K)[b4] = ko;
  ((float4*)V)[b4] = vv;
}

// ---------------- per-(head,chunk) local K^T V and K column sums ----------------
__global__ void chunk_sums_kernel(const float* __restrict__ Kg, const float* __restrict__ Vg,
                                  float* __restrict__ lkv, float* __restrict__ lks)
{
  extern __shared__ float smf[];
  float* Ks = smf;
  float* Vs = smf + CS * DH;
  const int hc = blockIdx.x, h = hc >> 4, c = hc & 15;
  const float* Kc = Kg + (size_t)(h * T + c * CS) * DH;
  const float* Vc = Vg + (size_t)(h * T + c * CS) * DH;
  const int tid = threadIdx.x;
  for (int idx = tid; idx < CS * DH / 4; idx += 256){
    ((float4*)Ks)[idx] = ((const float4*)Kc)[idx];
    ((float4*)Vs)[idx] = ((const float4*)Vc)[idx];
  }
  __syncthreads();

  const int m = tid & 63;
  const int dg = tid >> 6;
  float acc[16];
  #pragma unroll
  for (int i = 0; i < 16; i++) acc[i] = 0.f;
  for (int tt = 0; tt < CS; tt++){
    const float vv = Vs[tt * DH + m];
    #pragma unroll
    for (int i = 0; i < 16; i++)
      acc[i] += Ks[tt * DH + dg * 16 + i] * vv;
  }
  float* dst = lkv + (size_t)hc * DH * DH;
  #pragma unroll
  for (int i = 0; i < 16; i++)
    dst[(dg * 16 + i) * DH + m] = acc[i];

  if (tid < DH){
    float s = 0.f;
    for (int tt = 0; tt < CS; tt++) s += Ks[tt * DH + tid];
    lks[(size_t)hc * DH + tid] = s;
  }
}

// ---------------- exclusive prefix over chunks ----------------
__global__ void scan_kernel(const float* __restrict__ lkv, const float* __restrict__ lks,
                            float* __restrict__ Spre, float* __restrict__ zpre)
{
  const int h = blockIdx.x;
  for (int idx = threadIdx.x; idx < DH * DH; idx += blockDim.x){
    float acc = 0.f;
    for (int c = 0; c < NC; c++){
      const size_t o = (size_t)(h * NC + c) * DH * DH + idx;
      Spre[o] = acc;
      acc += lkv[o];
    }
  }
  for (int idx = threadIdx.x; idx < DH; idx += blockDim.x){
    float acc = 0.f;
    for (int c = 0; c < NC; c++){
      const size_t o = (size_t)(h * NC + c) * DH + idx;
      zpre[o] = acc;
      acc += lks[o];
    }
  }
}

// ---------------- per-(head,chunk) attention output -> hi/fp8 forms ----------------
__global__ void attn_kernel(const float* __restrict__ Qg, const float* __restrict__ Kg,
                            const float* __restrict__ Vg, const float* __restrict__ Spre,
                            const float* __restrict__ zpre)
{
  extern __shared__ float smf[];
  float* Qs  = smf;              // 128 x 65
  float* Ks  = Qs  + 128 * 65;   // 128 x 65 (later reused for V)
  float* As  = Ks  + 128 * 65;   // 128 x 130
  float* Sp  = As  + 128 * 130;  // 64 x 65
  float* zp  = Sp  + 64 * 65;    // 64
  float* dn  = zp  + 64;         // 128
  float* dnp = dn  + 128;        // 128 x 16

  const int hc = blockIdx.x, h = hc >> 4, c = hc & 15;
  const int tid = threadIdx.x;
  const float* Qc = Qg + (size_t)(h * T + c * CS) * DH;
  const float* Kc = Kg + (size_t)(h * T + c * CS) * DH;

  for (int idx = tid; idx < CS * DH / 4; idx += 256){
    const int r = idx >> 4, c4 = (idx & 15) << 2;
    float4 q = ((const float4*)Qc)[idx];
    float4 k = ((const float4*)Kc)[idx];
    float* qd = Qs + r * 65 + c4;
    qd[0] = q.x; qd[1] = q.y; qd[2] = q.z; qd[3] = q.w;
    float* kd = Ks + r * 65 + c4;
    kd[0] = k.x; kd[1] = k.y; kd[2] = k.z; kd[3] = k.w;
  }
  const float* SpG = Spre + (size_t)hc * DH * DH;
  for (int idx = tid; idx < DH * DH; idx += 256)
    Sp[(idx >> 6) * 65 + (idx & 63)] = SpG[idx];
  if (tid < 64) zp[tid] = zpre[(size_t)hc * DH + tid];
  __syncthreads();

  if (tid < 128){
    float s = 0.f;
    #pragma unroll
    for (int d = 0; d < 64; d++) s += Qs[tid * 65 + d] * zp[d];
    dn[tid] = s;
  }
  __syncthreads();

  const int tx = tid & 15, ty = tid >> 4;
  {
    float acc[8][8];
    #pragma unroll
    for (int i = 0; i < 8; i++)
      #pragma unroll
      for (int j = 0; j < 8; j++) acc[i][j] = 0.f;
    for (int d = 0; d < 64; d++){
      float a[8], b[8];
      #pragma unroll
      for (int i = 0; i < 8; i++) a[i] = Qs[(ty * 8 + i) * 65 + d];
      #pragma unroll
      for (int j = 0; j < 8; j++) b[j] = Ks[(tx * 8 + j) * 65 + d];
      #pragma unroll
      for (int i = 0; i < 8; i++)
        #pragma unroll
        for (int j = 0; j < 8; j++)
          acc[i][j] += a[i] * b[j];
    }
    #pragma unroll
    for (int i = 0; i < 8; i++){
      const int r = ty * 8 + i;
      float rs = 0.f;
      #pragma unroll
      for (int j = 0; j < 8; j++){
        const int s_ = tx * 8 + j;
        const float v = (s_ <= r) ? acc[i][j] : 0.f;
        As[r * 130 + s_] = v;
        rs += v;
      }
      dnp[r * 16 + tx] = rs;
    }
  }
  __syncthreads();

  {
    const float* Vc = Vg + (size_t)(h * T + c * CS) * DH;
    for (int idx = tid; idx < CS * DH / 4; idx += 256){
      const int r = idx >> 4, c4 = (idx & 15) << 2;
      float4 v = ((const float4*)Vc)[idx];
      float* vd = Ks + r * 65 + c4;
      vd[0] = v.x; vd[1] = v.y; vd[2] = v.z; vd[3] = v.w;
    }
    if (tid < 128){
      float s = dn[tid];
      #pragma unroll
      for (int xx = 0; xx < 16; xx++) s += dnp[tid * 16 + xx];
      dn[tid] = s + 1e-5f;
    }
  }
  __syncthreads();

  {
    float acc2[8][4];
    #pragma unroll
    for (int i = 0; i < 8; i++)
      #pragma unroll
      for (int j = 0; j < 4; j++) acc2[i][j] = 0.f;
    const int m0 = tx * 4, r0 = ty * 8;
    for (int s = 0; s < 128; s++){
      float vv[4];
      #pragma unroll
      for (int jj = 0; jj < 4; jj++) vv[jj] = Ks[s * 65 + m0 + jj];
      #pragma unroll
      for (int i = 0; i < 8; i++){
        const float av = As[(r0 + i) * 130 + s];
        #pragma unroll
        for (int jj = 0; jj < 4; jj++) acc2[i][jj] += av * vv[jj];
      }
    }
    for (int d = 0; d < 64; d++){
      float sp[4];
      #pragma unroll
      for (int jj = 0; jj < 4; jj++) sp[jj] = Sp[d * 65 + m0 + jj];
      #pragma unroll
      for (int i = 0; i < 8; i++){
        const float qv = Qs[(r0 + i) * 65 + d];
        #pragma unroll
        for (int jj = 0; jj < 4; jj++) acc2[i][jj] += qv * sp[jj];
      }
    }
    const size_t obase = (size_t)(c * CS) * D + h * DH;
    #pragma unroll
    for (int i = 0; i < 8; i++){
      const float inv = 1.f / dn[r0 + i];
      float o[4];
      #pragma unroll
      for (int jj = 0; jj < 4; jj++) o[jj] = acc2[i][jj] * inv;
      const size_t ptr = obase + (size_t)(r0 + i) * D + m0;
      emit_split4(o, g_ah, (uint32_t*)g_a8, (uint32_t*)g_al8, ptr >> 2);
    }
  }
}

// ---------------- launch ----------------
extern "C" void kernel_launch(void* const* d_in, const int* in_sizes, int n_in,
                              void* d_out, int out_size)
{
  (void)in_sizes; (void)n_in; (void)out_size;
  const float* x      = (const float*)d_in[0];
  const float* ln_g   = (const float*)d_in[1];
  const float* ln_b   = (const float*)d_in[2];
  const float* qkv_w  = (const float*)d_in[3];
  const float* qkv_b  = (const float*)d_in[4];
  const float* gate_w = (const float*)d_in[5];
  const float* gate_b = (const float*)d_in[6];
  const float* proj_w = (const float*)d_in[7];
  const float* proj_b = (const float*)d_in[8];
  float* out = (float*)d_out;

  float *gate, *qkv, *Q, *K, *V, *lkv, *lks, *Spre, *zpre;
  __nv_bfloat16 *xh, *xnh, *ah, *qwh, *gwh, *pwh;
  uint8_t *x8, *xl8, *xn8, *xnl8, *a8, *al8, *qw8, *qwl8, *gw8, *gwl8, *pw8, *pwl8;
  cudaGetSymbolAddress((void**)&gate, g_gate);
  cudaGetSymbolAddress((void**)&qkv,  g_qkv);
  cudaGetSymbolAddress((void**)&Q,    g_Q);
  cudaGetSymbolAddress((void**)&K,    g_K);
  cudaGetSymbolAddress((void**)&V,    g_V);
  cudaGetSymbolAddress((void**)&lkv,  g_lkv);
  cudaGetSymbolAddress((void**)&lks,  g_lks);
  cudaGetSymbolAddress((void**)&Spre, g_Spre);
  cudaGetSymbolAddress((void**)&zpre, g_zpre);
  cudaGetSymbolAddress((void**)&xh,   g_xh);
  cudaGetSymbolAddress((void**)&x8,   g_x8);
  cudaGetSymbolAddress((void**)&xl8,  g_xl8);
  cudaGetSymbolAddress((void**)&xnh,  g_xnh);
  cudaGetSymbolAddress((void**)&xn8,  g_xn8);
  cudaGetSymbolAddress((void**)&xnl8, g_xnl8);
  cudaGetSymbolAddress((void**)&ah,   g_ah);
  cudaGetSymbolAddress((void**)&a8,   g_a8);
  cudaGetSymbolAddress((void**)&al8,  g_al8);
  cudaGetSymbolAddress((void**)&qwh,  g_qwh);
  cudaGetSymbolAddress((void**)&qw8,  g_qw8);
  cudaGetSymbolAddress((void**)&qwl8, g_qwl8);
  cudaGetSymbolAddress((void**)&gwh,  g_gwh);
  cudaGetSymbolAddress((void**)&gw8,  g_gw8);
  cudaGetSymbolAddress((void**)&gwl8, g_gwl8);
  cudaGetSymbolAddress((void**)&pwh,  g_pwh);
  cudaGetSymbolAddress((void**)&pw8,  g_pw8);
  cudaGetSymbolAddress((void**)&pwl8, g_pwl8);

  const int CHUNK_SMEM = 2 * CS * DH * 4;
  const int ATTN_SMEM  = (128*65 + 128*65 + 128*130 + 64*65 + 64 + 128 + 128*16) * 4;
  cudaFuncSetAttribute(chunk_sums_kernel, cudaFuncAttributeMaxDynamicSharedMemorySize, CHUNK_SMEM);
  cudaFuncSetAttribute(attn_kernel,       cudaFuncAttributeMaxDynamicSharedMemorySize, ATTN_SMEM);
  cudaFuncSetAttribute(hmma_gemm_dual,    cudaFuncAttributeMaxDynamicSharedMemorySize, GEMM_SMEM);

  split_all_kernel<<<(X4 + Q4 + G4 + P4) / 256, 256>>>(x, qkv_w, gate_w, proj_w);
  ln_kernel<<<T, 256>>>(x, ln_g, ln_b);

  GArgs gateArgs = { xh,  x8,  xl8,  gwh, gw8, gwl8, gate_b, gate, D,     1 };
  GArgs qkvArgs  = { xnh, xn8, xnl8, qwh, qw8, qwl8, qkv_b,  qkv,  3 * D, 0 };
  hmma_gemm_dual<<<dim3(8 + 24, T / 128), 256, GEMM_SMEM>>>(gateArgs, qkvArgs, 8);

  prep_kernel<<<T, 256>>>(gate, qkv, Q, K, V);
  chunk_sums_kernel<<<H * NC, 256, CHUNK_SMEM>>>(K, V, lkv, lks);
  scan_kernel<<<H, 256>>>(lkv, lks, Spre, zpre);
  attn_kernel<<<H * NC, 256, ATTN_SMEM>>>(Q, K, V, Spre, zpre);

  GArgs projArgs = { ah, a8, al8, pwh, pw8, pwl8, proj_b, out, D, 0 };
  hmma_gemm_dual<<<dim3(8, T / 128), 256, GEMM_SMEM>>>(projArgs, projArgs, 8);
}

// round 7
// speedup vs baseline: 1.4125x; 1.4125x over previous
#include <cuda_runtime.h>
#include <cuda_fp16.h>
#include <cstdint>
#include <math.h>

#define T 2048
#define D 1024
#define H 16
#define DH 64
#define NC 16
#define CS 128
#define GK 1024
#define LO_SCALE 2048.0f
#define INV_LO_SCALE (1.0f/2048.0f)

// ---------------- scratch (no allocations allowed) ----------------
__device__ float g_gate[T*D];
__device__ float g_qkv[T*3*D];
__device__ float g_Q[T*D];
__device__ float g_K[T*D];
__device__ float g_V[T*D];
__device__ float g_lkv[H*NC*DH*DH];
__device__ float g_lks[H*NC*DH];
__device__ float g_Spre[H*NC*DH*DH];
__device__ float g_zpre[H*NC*DH];

// fp16 activations (single-rounded) and fp16 hi/lo weight splits (lo pre-scaled 2^11)
__device__ __half g_xa[T*D];          // fp16(x)
__device__ __half g_xna[T*D];         // fp16(ln(x))
__device__ __half g_aa[T*D];          // fp16(attn out)
__device__ __half g_qwh[3*D*D], g_qwl[3*D*D];
__device__ __half g_gwh[D*D],   g_gwl[D*D];
__device__ __half g_pwh[D*D],   g_pwl[D*D];

// ---------------- helpers ----------------
__device__ __forceinline__ uint32_t smem_u32(const void* p){
  uint32_t a;
  asm("{ .reg .u64 t; cvta.to.shared.u64 t, %1; cvt.u32.u64 %0, t; }" : "=r"(a) : "l"(p));
  return a;
}
__device__ __forceinline__ float elu1f(float x){ return x > 0.f ? x + 1.f : expf(x); }

__device__ __forceinline__ void ldsm_x4(uint32_t* r, uint32_t addr){
  asm volatile("ldmatrix.sync.aligned.m8n8.x4.shared.b16 {%0,%1,%2,%3}, [%4];"
    : "=r"(r[0]), "=r"(r[1]), "=r"(r[2]), "=r"(r[3]) : "r"(addr));
}
__device__ __forceinline__ void mma_f16(float* c, const uint32_t* a, const uint32_t* b){
  asm volatile(
    "mma.sync.aligned.m16n8k16.row.col.f32.f16.f16.f32 "
    "{%0,%1,%2,%3},{%4,%5,%6,%7},{%8,%9},{%0,%1,%2,%3};"
    : "+f"(c[0]), "+f"(c[1]), "+f"(c[2]), "+f"(c[3])
    : "r"(a[0]), "r"(a[1]), "r"(a[2]), "r"(a[3]), "r"(b[0]), "r"(b[1]));
}
__device__ __forceinline__ void cp16(uint32_t smem, const void* gmem){
  asm volatile("cp.async.cg.shared.global [%0], [%1], 16;" :: "r"(smem), "l"(gmem));
}
__device__ __forceinline__ void cp_commit(){
  asm volatile("cp.async.commit_group;" ::: "memory");
}
template<int N>
__device__ __forceinline__ void cp_wait(){
  asm volatile("cp.async.wait_group %0;" :: "n"(N) : "memory");
}

// ---------------- fused split: x -> fp16; weights -> fp16 hi + scaled lo ----------------
#define X4 (T*D/4)
#define Q4 (3*D*D/4)
#define G4 (D*D/4)
#define P4 (D*D/4)
__global__ void split_all_kernel(const float* __restrict__ x, const float* __restrict__ qw,
                                 const float* __restrict__ gw, const float* __restrict__ pw)
{
  int i = blockIdx.x * 256 + threadIdx.x;
  if (i < X4){
    float4 v = ((const float4*)x)[i];
    ((__half2*)g_xa)[i*2]   = __floats2half2_rn(v.x, v.y);
    ((__half2*)g_xa)[i*2+1] = __floats2half2_rn(v.z, v.w);
    return;
  }
  const float* src; __half *hp, *lp; int j;
  if (i < X4 + Q4){ src = qw; hp = g_qwh; lp = g_qwl; j = i - X4; }
  else if (i < X4 + Q4 + G4){ src = gw; hp = g_gwh; lp = g_gwl; j = i - (X4 + Q4); }
  else { src = pw; hp = g_pwh; lp = g_pwl; j = i - (X4 + Q4 + G4); }
  float4 v4 = ((const float4*)src)[j];
  float v[4] = {v4.x, v4.y, v4.z, v4.w};
  __half hv[4]; float lv[4];
  #pragma unroll
  for (int k = 0; k < 4; k++){
    hv[k] = __float2half_rn(v[k]);
    lv[k] = (v[k] - __half2float(hv[k])) * LO_SCALE;
  }
  ((__half2*)hp)[j*2]   = __halves2half2(hv[0], hv[1]);
  ((__half2*)hp)[j*2+1] = __halves2half2(hv[2], hv[3]);
  ((__half2*)lp)[j*2]   = __floats2half2_rn(lv[0], lv[1]);
  ((__half2*)lp)[j*2+1] = __floats2half2_rn(lv[2], lv[3]);
}

// ---------------- LayerNorm -> fp16 ----------------
__global__ void ln_kernel(const float* __restrict__ x, const float* __restrict__ g,
                          const float* __restrict__ b)
{
  __shared__ float red[16];
  const int t = blockIdx.x;
  const int i = threadIdx.x;
  float4 xv = ((const float4*)(x + (size_t)t*D))[i];
  float s  = xv.x + xv.y + xv.z + xv.w;
  float s2 = xv.x*xv.x + xv.y*xv.y + xv.z*xv.z + xv.w*xv.w;
  const int lane = i & 31, w = i >> 5;
  #pragma unroll
  for (int o = 16; o; o >>= 1){
    s  += __shfl_xor_sync(0xffffffffu, s,  o);
    s2 += __shfl_xor_sync(0xffffffffu, s2, o);
  }
  if (lane == 0){ red[w] = s; red[8+w] = s2; }
  __syncthreads();
  if (i == 0){
    float a = 0.f, c = 0.f;
    #pragma unroll
    for (int k = 0; k < 8; k++){ a += red[k]; c += red[8+k]; }
    red[0] = a; red[8] = c;
  }
  __syncthreads();
  const float mu   = red[0] * (1.f / D);
  const float var  = red[8] * (1.f / D) - mu * mu;
  const float rstd = rsqrtf(var + 1e-5f);
  float4 gv = ((const float4*)g)[i];
  float4 bv = ((const float4*)b)[i];
  float o0 = (xv.x - mu) * rstd * gv.x + bv.x;
  float o1 = (xv.y - mu) * rstd * gv.y + bv.y;
  float o2 = (xv.z - mu) * rstd * gv.z + bv.z;
  float o3 = (xv.w - mu) * rstd * gv.w + bv.w;
  const size_t idx4 = ((size_t)t*D >> 2) + i;
  ((__half2*)g_xna)[idx4*2]   = __floats2half2_rn(o0, o1);
  ((__half2*)g_xna)[idx4*2+1] = __floats2half2_rn(o2, o3);
}

// ---------------- HMMA GEMM: C[2048,N] = A[2048,1024] @ B[N,1024]^T ----------------
// fp16 2-term: C = A·Bh + (A·Bl_scaled)/2048 + bias
// Block tile 128x128, BK=32, 8 warps of 64x32, 4-stage cp.async ring.
#define PITCH 80           // bytes per SMEM row (64B data + 16B pad)
#define ARR   (128*PITCH)  // 10240 B per array
#define OFF_A  0
#define OFF_BH (ARR)
#define OFF_BL (2*ARR)
#define STAGE  (3*ARR)     // 30720 B
#define NRING 4
#define NKT   (GK/32)      // 32 k-tiles
#define GEMM_SMEM (NRING*STAGE)  // 122880 B

struct GArgs {
  const __half* A;
  const __half* Bh;
  const __half* Bl;
  const float* bias;
  float* C;
  int N;
  int sig;
};

__device__ __forceinline__ void gemm_load_stage(uint32_t sbase,
    const __half* A, const __half* Bh, const __half* Bl,
    int kt, int tid)
{
  const int koff = kt * 32;
  const __half* srcs[3] = {A, Bh, Bl};
  #pragma unroll
  for (int arr = 0; arr < 3; arr++){
    const __half* s = srcs[arr] + koff;
    #pragma unroll
    for (int it = 0; it < 2; it++){
      const int w = tid + it * 256;      // 0..511
      const int row = w >> 2, c16 = w & 3;
      cp16(sbase + arr*ARR + row*PITCH + c16*16,
           s + (size_t)row * GK + c16*8);
    }
  }
}

__global__ void __launch_bounds__(256, 1)
hmma_gemm_dual(GArgs g0, GArgs g1, int split)
{
  extern __shared__ __align__(128) char sm[];
  const uint32_t sb = smem_u32(sm);
  const int tid = threadIdx.x;
  const int wid = tid >> 5, lane = tid & 31;
  const int wm = wid & 1, wn = wid >> 1;
  const int m0w = wm * 64, n0w = wn * 32;

  const bool first = ((int)blockIdx.x < split);
  const GArgs ga = first ? g0 : g1;
  const int bxn = first ? (int)blockIdx.x : (int)blockIdx.x - split;
  const int bn0 = bxn << 7, bm0 = blockIdx.y << 7;

  const __half* pA  = ga.A  + (size_t)bm0 * GK;
  const __half* pBh = ga.Bh + (size_t)bn0 * GK;
  const __half* pBl = ga.Bl + (size_t)bn0 * GK;

  float acc[4][4][4], accc[4][4][4];
  #pragma unroll
  for (int i = 0; i < 4; i++)
    #pragma unroll
    for (int j = 0; j < 4; j++)
      #pragma unroll
      for (int q = 0; q < 4; q++){ acc[i][j][q] = 0.f; accc[i][j][q] = 0.f; }

  // ldmatrix per-lane offsets
  const int rowA = lane & 15;
  const uint32_t colA = (lane >> 4) << 4;                 // 0 or 16 bytes
  const int rowB = (lane & 7) + (((lane >> 4) & 1) << 3); // 0..15
  const uint32_t colB = ((lane >> 3) & 1) << 4;           // 0 or 16 bytes

  gemm_load_stage(sb + 0*STAGE, pA, pBh, pBl, 0, tid); cp_commit();
  gemm_load_stage(sb + 1*STAGE, pA, pBh, pBl, 1, tid); cp_commit();
  gemm_load_stage(sb + 2*STAGE, pA, pBh, pBl, 2, tid); cp_commit();

  for (int kt = 0; kt < NKT; kt++){
    cp_wait<2>();
    __syncthreads();

    if (kt + 3 < NKT)
      gemm_load_stage(sb + ((kt + 3) & (NRING-1)) * STAGE, pA, pBh, pBl, kt + 3, tid);
    cp_commit();

    const uint32_t st = sb + (kt & (NRING-1)) * STAGE;
    const uint32_t aB  = st + OFF_A  + (m0w + rowA) * PITCH + colA;
    const uint32_t bhB = st + OFF_BH + (n0w + rowB) * PITCH + colB;
    const uint32_t blB = st + OFF_BL + (n0w + rowB) * PITCH + colB;

    #pragma unroll
    for (int ks = 0; ks < 2; ks++){
      const uint32_t kb = ks * 32;
      uint32_t a16[4][4], bh16[4][2], bl16[4][2];
      #pragma unroll
      for (int mi = 0; mi < 4; mi++)
        ldsm_x4(a16[mi], aB + mi*16*PITCH + kb);
      #pragma unroll
      for (int p = 0; p < 2; p++){
        uint32_t r[4];
        ldsm_x4(r, bhB + p*16*PITCH + kb);
        bh16[2*p][0] = r[0]; bh16[2*p][1] = r[1];
        bh16[2*p+1][0] = r[2]; bh16[2*p+1][1] = r[3];
        ldsm_x4(r, blB + p*16*PITCH + kb);
        bl16[2*p][0] = r[0]; bl16[2*p][1] = r[1];
        bl16[2*p+1][0] = r[2]; bl16[2*p+1][1] = r[3];
      }
      // main term
      #pragma unroll
      for (int mi = 0; mi < 4; mi++)
        #pragma unroll
        for (int nj = 0; nj < 4; nj++)
          mma_f16(acc[mi][nj], a16[mi], bh16[nj]);
      // correction term (lo pre-scaled)
      #pragma unroll
      for (int mi = 0; mi < 4; mi++)
        #pragma unroll
        for (int nj = 0; nj < 4; nj++)
          mma_f16(accc[mi][nj], a16[mi], bl16[nj]);
    }
  }

  // epilogue
  const int g = lane >> 2, t4 = lane & 3;
  #pragma unroll
  for (int mi = 0; mi < 4; mi++){
    #pragma unroll
    for (int nj = 0; nj < 4; nj++){
      const int row = bm0 + m0w + mi*16 + g;
      const int col = bn0 + n0w + nj*8 + t4*2;
      float b0 = ga.bias[col], b1 = ga.bias[col+1];
      float o0 = acc[mi][nj][0] + accc[mi][nj][0] * INV_LO_SCALE + b0;
      float o1 = acc[mi][nj][1] + accc[mi][nj][1] * INV_LO_SCALE + b1;
      float o2 = acc[mi][nj][2] + accc[mi][nj][2] * INV_LO_SCALE + b0;
      float o3 = acc[mi][nj][3] + accc[mi][nj][3] * INV_LO_SCALE + b1;
      if (ga.sig){
        o0 = 1.f / (1.f + expf(-o0)); o1 = 1.f / (1.f + expf(-o1));
        o2 = 1.f / (1.f + expf(-o2)); o3 = 1.f / (1.f + expf(-o3));
      }
      *(float2*)(ga.C + (size_t)row * ga.N + col)       = make_float2(o0, o1);
      *(float2*)(ga.C + (size_t)(row + 8) * ga.N + col) = make_float2(o2, o3);
    }
  }
}

// ---------------- gate-normalize + apply + elu+1 + head split ----------------
__global__ void prep_kernel(const float* __restrict__ gate, const float* __restrict__ qkv,
                            float* __restrict__ Q, float* __restrict__ K, float* __restrict__ V)
{
  __shared__ float red[8];
  const int t = blockIdx.x, i = threadIdx.x;
  float4 gv = ((const float4*)(gate + (size_t)t*D))[i];
  float s = gv.x + gv.y + gv.z + gv.w;
  const int lane = i & 31, w = i >> 5;
  #pragma unroll
  for (int o = 16; o; o >>= 1) s += __shfl_xor_sync(0xffffffffu, s, o);
  if (lane == 0) red[w] = s;
  __syncthreads();
  if (i == 0){
    float a = 0.f;
    #pragma unroll
    for (int k = 0; k < 8; k++) a += red[k];
    red[0] = a;
  }
  __syncthreads();
  const float inv = 1.f / (red[0] * (1.f / D) + 1e-5f);

  const float4* qrow = (const float4*)(qkv + (size_t)t * 3 * D);
  float4 qv = qrow[i], kv = qrow[i + 256], vv = qrow[i + 512];
  float4 qo, ko;
  qo.x = elu1f(qv.x * gv.x * inv); qo.y = elu1f(qv.y * gv.y * inv);
  qo.z = elu1f(qv.z * gv.z * inv); qo.w = elu1f(qv.w * gv.w * inv);
  ko.x = elu1f(kv.x * gv.x * inv); ko.y = elu1f(kv.y * gv.y * inv);
  ko.z = elu1f(kv.z * gv.z * inv); ko.w = elu1f(kv.w * gv.w * inv);

  const int h = i >> 4;
  const int dh = (i & 15) << 2;
  const size_t b4 = ((size_t)(h * T + t) * DH + dh) >> 2;
  ((float4*)Q)[b4] = qo;
  ((float4*)K)[b4] = ko;
  ((float4*)V)[b4] = vv;
}

// ---------------- per-(head,chunk) local K^T V and K column sums ----------------
__global__ void chunk_sums_kernel(const float* __restrict__ Kg, const float* __restrict__ Vg,
                                  float* __restrict__ lkv, float* __restrict__ lks)
{
  extern __shared__ float smf[];
  float* Ks = smf;
  float* Vs = smf + CS * DH;
  const int hc = blockIdx.x, h = hc >> 4, c = hc & 15;
  const float* Kc = Kg + (size_t)(h * T + c * CS) * DH;
  const float* Vc = Vg + (size_t)(h * T + c * CS) * DH;
  const int tid = threadIdx.x;
  for (int idx = tid; idx < CS * DH / 4; idx += 256){
    ((float4*)Ks)[idx] = ((const float4*)Kc)[idx];
    ((float4*)Vs)[idx] = ((const float4*)Vc)[idx];
  }
  __syncthreads();

  const int m = tid & 63;
  const int dg = tid >> 6;
  float acc[16];
  #pragma unroll
  for (int i = 0; i < 16; i++) acc[i] = 0.f;
  for (int tt = 0; tt < CS; tt++){
    const float vv = Vs[tt * DH + m];
    #pragma unroll
    for (int i = 0; i < 16; i++)
      acc[i] += Ks[tt * DH + dg * 16 + i] * vv;
  }
  float* dst = lkv + (size_t)hc * DH * DH;
  #pragma unroll
  for (int i = 0; i < 16; i++)
    dst[(dg * 16 + i) * DH + m] = acc[i];

  if (tid < DH){
    float s = 0.f;
    for (int tt = 0; tt < CS; tt++) s += Ks[tt * DH + tid];
    lks[(size_t)hc * DH + tid] = s;
  }
}

// ---------------- exclusive prefix over chunks ----------------
__global__ void scan_kernel(const float* __restrict__ lkv, const float* __restrict__ lks,
                            float* __restrict__ Spre, float* __restrict__ zpre)
{
  const int h = blockIdx.x;
  for (int idx = threadIdx.x; idx < DH * DH; idx += blockDim.x){
    float acc = 0.f;
    for (int c = 0; c < NC; c++){
      const size_t o = (size_t)(h * NC + c) * DH * DH + idx;
      Spre[o] = acc;
      acc += lkv[o];
    }
  }
  for (int idx = threadIdx.x; idx < DH; idx += blockDim.x){
    float acc = 0.f;
    for (int c = 0; c < NC; c++){
      const size_t o = (size_t)(h * NC + c) * DH + idx;
      zpre[o] = acc;
      acc += lks[o];
    }
  }
}

// ---------------- per-(head,chunk) attention output -> fp16 ----------------
__global__ void attn_kernel(const float* __restrict__ Qg, const float* __restrict__ Kg,
                            const float* __restrict__ Vg, const float* __restrict__ Spre,
                            const float* __restrict__ zpre)
{
  extern __shared__ float smf[];
  float* Qs  = smf;              // 128 x 65
  float* Ks  = Qs  + 128 * 65;   // 128 x 65 (later reused for V)
  float* As  = Ks  + 128 * 65;   // 128 x 130
  float* Sp  = As  + 128 * 130;  // 64 x 65
  float* zp  = Sp  + 64 * 65;    // 64
  float* dn  = zp  + 64;         // 128
  float* dnp = dn  + 128;        // 128 x 16

  const int hc = blockIdx.x, h = hc >> 4, c = hc & 15;
  const int tid = threadIdx.x;
  const float* Qc = Qg + (size_t)(h * T + c * CS) * DH;
  const float* Kc = Kg + (size_t)(h * T + c * CS) * DH;

  for (int idx = tid; idx < CS * DH / 4; idx += 256){
    const int r = idx >> 4, c4 = (idx & 15) << 2;
    float4 q = ((const float4*)Qc)[idx];
    float4 k = ((const float4*)Kc)[idx];
    float* qd = Qs + r * 65 + c4;
    qd[0] = q.x; qd[1] = q.y; qd[2] = q.z; qd[3] = q.w;
    float* kd = Ks + r * 65 + c4;
    kd[0] = k.x; kd[1] = k.y; kd[2] = k.z; kd[3] = k.w;
  }
  const float* SpG = Spre + (size_t)hc * DH * DH;
  for (int idx = tid; idx < DH * DH; idx += 256)
    Sp[(idx >> 6) * 65 + (idx & 63)] = SpG[idx];
  if (tid < 64) zp[tid] = zpre[(size_t)hc * DH + tid];
  __syncthreads();

  if (tid < 128){
    float s = 0.f;
    #pragma unroll
    for (int d = 0; d < 64; d++) s += Qs[tid * 65 + d] * zp[d];
    dn[tid] = s;
  }
  __syncthreads();

  const int tx = tid & 15, ty = tid >> 4;
  {
    float acc[8][8];
    #pragma unroll
    for (int i = 0; i < 8; i++)
      #pragma unroll
      for (int j = 0; j < 8; j++) acc[i][j] = 0.f;
    for (int d = 0; d < 64; d++){
      float a[8], b[8];
      #pragma unroll
      for (int i = 0; i < 8; i++) a[i] = Qs[(ty * 8 + i) * 65 + d];
      #pragma unroll
      for (int j = 0; j < 8; j++) b[j] = Ks[(tx * 8 + j) * 65 + d];
      #pragma unroll
      for (int i = 0; i < 8; i++)
        #pragma unroll
        for (int j = 0; j < 8; j++)
          acc[i][j] += a[i] * b[j];
    }
    #pragma unroll
    for (int i = 0; i < 8; i++){
      const int r = ty * 8 + i;
      float rs = 0.f;
      #pragma unroll
      for (int j = 0; j < 8; j++){
        const int s_ = tx * 8 + j;
        const float v = (s_ <= r) ? acc[i][j] : 0.f;
        As[r * 130 + s_] = v;
        rs += v;
      }
      dnp[r * 16 + tx] = rs;
    }
  }
  __syncthreads();

  {
    const float* Vc = Vg + (size_t)(h * T + c * CS) * DH;
    for (int idx = tid; idx < CS * DH / 4; idx += 256){
      const int r = idx >> 4, c4 = (idx & 15) << 2;
      float4 v = ((const float4*)Vc)[idx];
      float* vd = Ks + r * 65 + c4;
      vd[0] = v.x; vd[1] = v.y; vd[2] = v.z; vd[3] = v.w;
    }
    if (tid < 128){
      float s = dn[tid];
      #pragma unroll
      for (int xx = 0; xx < 16; xx++) s += dnp[tid * 16 + xx];
      dn[tid] = s + 1e-5f;
    }
  }
  __syncthreads();

  {
    float acc2[8][4];
    #pragma unroll
    for (int i = 0; i < 8; i++)
      #pragma unroll
      for (int j = 0; j < 4; j++) acc2[i][j] = 0.f;
    const int m0 = tx * 4, r0 = ty * 8;
    for (int s = 0; s < 128; s++){
      float vv[4];
      #pragma unroll
      for (int jj = 0; jj < 4; jj++) vv[jj] = Ks[s * 65 + m0 + jj];
      #pragma unroll
      for (int i = 0; i < 8; i++){
        const float av = As[(r0 + i) * 130 + s];
        #pragma unroll
        for (int jj = 0; jj < 4; jj++) acc2[i][jj] += av * vv[jj];
      }
    }
    for (int d = 0; d < 64; d++){
      float sp[4];
      #pragma unroll
      for (int jj = 0; jj < 4; jj++) sp[jj] = Sp[d * 65 + m0 + jj];
      #pragma unroll
      for (int i = 0; i < 8; i++){
        const float qv = Qs[(r0 + i) * 65 + d];
        #pragma unroll
        for (int jj = 0; jj < 4; jj++) acc2[i][jj] += qv * sp[jj];
      }
    }
    const size_t obase = (size_t)(c * CS) * D + h * DH;
    #pragma unroll
    for (int i = 0; i < 8; i++){
      const float inv = 1.f / dn[r0 + i];
      const size_t ptr = obase + (size_t)(r0 + i) * D + m0;
      *(__half2*)&g_aa[ptr]     = __floats2half2_rn(acc2[i][0] * inv, acc2[i][1] * inv);
      *(__half2*)&g_aa[ptr + 2] = __floats2half2_rn(acc2[i][2] * inv, acc2[i][3] * inv);
    }
  }
}

// ---------------- launch ----------------
extern "C" void kernel_launch(void* const* d_in, const int* in_sizes, int n_in,
                              void* d_out, int out_size)
{
  (void)in_sizes; (void)n_in; (void)out_size;
  const float* x      = (const float*)d_in[0];
  const float* ln_g   = (const float*)d_in[1];
  const float* ln_b   = (const float*)d_in[2];
  const float* qkv_w  = (const float*)d_in[3];
  const float* qkv_b  = (const float*)d_in[4];
  const float* gate_w = (const float*)d_in[5];
  const float* gate_b = (const float*)d_in[6];
  const float* proj_w = (const float*)d_in[7];
  const float* proj_b = (const float*)d_in[8];
  float* out = (float*)d_out;

  float *gate, *qkv, *Q, *K, *V, *lkv, *lks, *Spre, *zpre;
  __half *xa, *xna, *aa, *qwh, *qwl, *gwh, *gwl, *pwh, *pwl;
  cudaGetSymbolAddress((void**)&gate, g_gate);
  cudaGetSymbolAddress((void**)&qkv,  g_qkv);
  cudaGetSymbolAddress((void**)&Q,    g_Q);
  cudaGetSymbolAddress((void**)&K,    g_K);
  cudaGetSymbolAddress((void**)&V,    g_V);
  cudaGetSymbolAddress((void**)&lkv,  g_lkv);
  cudaGetSymbolAddress((void**)&lks,  g_lks);
  cudaGetSymbolAddress((void**)&Spre, g_Spre);
  cudaGetSymbolAddress((void**)&zpre, g_zpre);
  cudaGetSymbolAddress((void**)&xa,   g_xa);
  cudaGetSymbolAddress((void**)&xna,  g_xna);
  cudaGetSymbolAddress((void**)&aa,   g_aa);
  cudaGetSymbolAddress((void**)&qwh,  g_qwh);
  cudaGetSymbolAddress((void**)&qwl,  g_qwl);
  cudaGetSymbolAddress((void**)&gwh,  g_gwh);
  cudaGetSymbolAddress((void**)&gwl,  g_gwl);
  cudaGetSymbolAddress((void**)&pwh,  g_pwh);
  cudaGetSymbolAddress((void**)&pwl,  g_pwl);

  const int CHUNK_SMEM = 2 * CS * DH * 4;
  const int ATTN_SMEM  = (128*65 + 128*65 + 128*130 + 64*65 + 64 + 128 + 128*16) * 4;
  cudaFuncSetAttribute(chunk_sums_kernel, cudaFuncAttributeMaxDynamicSharedMemorySize, CHUNK_SMEM);
  cudaFuncSetAttribute(attn_kernel,       cudaFuncAttributeMaxDynamicSharedMemorySize, ATTN_SMEM);
  cudaFuncSetAttribute(hmma_gemm_dual,    cudaFuncAttributeMaxDynamicSharedMemorySize, GEMM_SMEM);

  split_all_kernel<<<(X4 + Q4 + G4 + P4) / 256, 256>>>(x, qkv_w, gate_w, proj_w);
  ln_kernel<<<T, 256>>>(x, ln_g, ln_b);

  GArgs gateArgs = { xa,  gwh, gwl, gate_b, gate, D,     1 };
  GArgs qkvArgs  = { xna, qwh, qwl, qkv_b,  qkv,  3 * D, 0 };
  hmma_gemm_dual<<<dim3(8 + 24, T / 128), 256, GEMM_SMEM>>>(gateArgs, qkvArgs, 8);

  prep_kernel<<<T, 256>>>(gate, qkv, Q, K, V);
  chunk_sums_kernel<<<H * NC, 256, CHUNK_SMEM>>>(K, V, lkv, lks);
  scan_kernel<<<H, 256>>>(lkv, lks, Spre, zpre);
  attn_kernel<<<H * NC, 256, ATTN_SMEM>>>(Q, K, V, Spre, zpre);

  GArgs projArgs = { aa, pwh, pwl, proj_b, out, D, 0 };
  hmma_gemm_dual<<<dim3(8, T / 128), 256, GEMM_SMEM>>>(projArgs, projArgs, 8);
}

// round 8
// speedup vs baseline: 1.6877x; 1.1948x over previous
#include <cuda_runtime.h>
#include <cuda_fp16.h>
#include <cstdint>
#include <math.h>

#define T 2048
#define D 1024
#define H 16
#define DH 64
#define NC 16
#define CS 128
#define GK 1024
#define LO_SCALE 2048.0f
#define INV_LO_SCALE (1.0f/2048.0f)

// ---------------- scratch (no allocations allowed) ----------------
__device__ float g_gate[T*D];
__device__ float g_qkv[T*3*D];
__device__ float g_Q[T*D];
__device__ float g_K[T*D];
__device__ float g_V[T*D];
__device__ float g_lkv[H*NC*DH*DH];
__device__ float g_lks[H*NC*DH];
__device__ float g_Spre[H*NC*DH*DH];
__device__ float g_zpre[H*NC*DH];

// fp16 activations (single-rounded); weights fp16 (gate/qkv single, proj hi+lo)
__device__ __half g_xa[T*D];          // fp16(x)
__device__ __half g_xna[T*D];         // fp16(ln(x))
__device__ __half g_aa[T*D];          // fp16(attn out)
__device__ __half g_qwh[3*D*D];
__device__ __half g_gwh[D*D];
__device__ __half g_pwh[D*D], g_pwl[D*D];

// ---------------- helpers ----------------
__device__ __forceinline__ uint32_t smem_u32(const void* p){
  uint32_t a;
  asm("{ .reg .u64 t; cvta.to.shared.u64 t, %1; cvt.u32.u64 %0, t; }" : "=r"(a) : "l"(p));
  return a;
}
__device__ __forceinline__ float elu1f(float x){ return x > 0.f ? x + 1.f : expf(x); }

__device__ __forceinline__ void ldsm_x4(uint32_t* r, uint32_t addr){
  asm volatile("ldmatrix.sync.aligned.m8n8.x4.shared.b16 {%0,%1,%2,%3}, [%4];"
    : "=r"(r[0]), "=r"(r[1]), "=r"(r[2]), "=r"(r[3]) : "r"(addr));
}
__device__ __forceinline__ void mma_f16(float* c, const uint32_t* a, const uint32_t* b){
  asm volatile(
    "mma.sync.aligned.m16n8k16.row.col.f32.f16.f16.f32 "
    "{%0,%1,%2,%3},{%4,%5,%6,%7},{%8,%9},{%0,%1,%2,%3};"
    : "+f"(c[0]), "+f"(c[1]), "+f"(c[2]), "+f"(c[3])
    : "r"(a[0]), "r"(a[1]), "r"(a[2]), "r"(a[3]), "r"(b[0]), "r"(b[1]));
}
__device__ __forceinline__ void cp16(uint32_t smem, const void* gmem){
  asm volatile("cp.async.cg.shared.global [%0], [%1], 16;" :: "r"(smem), "l"(gmem));
}
__device__ __forceinline__ void cp_commit(){
  asm volatile("cp.async.commit_group;" ::: "memory");
}
template<int N>
__device__ __forceinline__ void cp_wait(){
  asm volatile("cp.async.wait_group %0;" :: "n"(N) : "memory");
}

// ---------------- fused split: x -> fp16; gate/qkv w -> fp16; proj w -> fp16 hi+lo ----------------
#define X4 (T*D/4)
#define Q4 (3*D*D/4)
#define G4 (D*D/4)
#define P4 (D*D/4)
__global__ void split_all_kernel(const float* __restrict__ x, const float* __restrict__ qw,
                                 const float* __restrict__ gw, const float* __restrict__ pw)
{
  int i = blockIdx.x * 256 + threadIdx.x;
  if (i < X4 + Q4 + G4){
    const float* src; __half* hp; int j;
    if (i < X4){ src = x; hp = g_xa; j = i; }
    else if (i < X4 + Q4){ src = qw; hp = g_qwh; j = i - X4; }
    else { src = gw; hp = g_gwh; j = i - (X4 + Q4); }
    float4 v = ((const float4*)src)[j];
    ((__half2*)hp)[j*2]   = __floats2half2_rn(v.x, v.y);
    ((__half2*)hp)[j*2+1] = __floats2half2_rn(v.z, v.w);
    return;
  }
  // proj weights: hi + scaled lo
  int j = i - (X4 + Q4 + G4);
  float4 v4 = ((const float4*)pw)[j];
  float v[4] = {v4.x, v4.y, v4.z, v4.w};
  __half hv[4]; float lv[4];
  #pragma unroll
  for (int k = 0; k < 4; k++){
    hv[k] = __float2half_rn(v[k]);
    lv[k] = (v[k] - __half2float(hv[k])) * LO_SCALE;
  }
  ((__half2*)g_pwh)[j*2]   = __halves2half2(hv[0], hv[1]);
  ((__half2*)g_pwh)[j*2+1] = __halves2half2(hv[2], hv[3]);
  ((__half2*)g_pwl)[j*2]   = __floats2half2_rn(lv[0], lv[1]);
  ((__half2*)g_pwl)[j*2+1] = __floats2half2_rn(lv[2], lv[3]);
}

// ---------------- LayerNorm -> fp16 ----------------
__global__ void ln_kernel(const float* __restrict__ x, const float* __restrict__ g,
                          const float* __restrict__ b)
{
  __shared__ float red[16];
  const int t = blockIdx.x;
  const int i = threadIdx.x;
  float4 xv = ((const float4*)(x + (size_t)t*D))[i];
  float s  = xv.x + xv.y + xv.z + xv.w;
  float s2 = xv.x*xv.x + xv.y*xv.y + xv.z*xv.z + xv.w*xv.w;
  const int lane = i & 31, w = i >> 5;
  #pragma unroll
  for (int o = 16; o; o >>= 1){
    s  += __shfl_xor_sync(0xffffffffu, s,  o);
    s2 += __shfl_xor_sync(0xffffffffu, s2, o);
  }
  if (lane == 0){ red[w] = s; red[8+w] = s2; }
  __syncthreads();
  if (i == 0){
    float a = 0.f, c = 0.f;
    #pragma unroll
    for (int k = 0; k < 8; k++){ a += red[k]; c += red[8+k]; }
    red[0] = a; red[8] = c;
  }
  __syncthreads();
  const float mu   = red[0] * (1.f / D);
  const float var  = red[8] * (1.f / D) - mu * mu;
  const float rstd = rsqrtf(var + 1e-5f);
  float4 gv = ((const float4*)g)[i];
  float4 bv = ((const float4*)b)[i];
  float o0 = (xv.x - mu) * rstd * gv.x + bv.x;
  float o1 = (xv.y - mu) * rstd * gv.y + bv.y;
  float o2 = (xv.z - mu) * rstd * gv.z + bv.z;
  float o3 = (xv.w - mu) * rstd * gv.w + bv.w;
  const size_t idx4 = ((size_t)t*D >> 2) + i;
  ((__half2*)g_xna)[idx4*2]   = __floats2half2_rn(o0, o1);
  ((__half2*)g_xna)[idx4*2+1] = __floats2half2_rn(o2, o3);
}

// ---------------- HMMA GEMM: C[2048,N] = A[2048,1024] @ B[N,1024]^T ----------------
// TWO=0: C = A·Bh + bias            (single fp16 term)
// TWO=1: C = A·Bh + (A·Bl)/2048 + b (weight-split corrected)
// Block tile 128x128, BK=32, 8 warps of 64x32, 4-stage cp.async ring.
#define PITCH 80           // bytes per SMEM row (64B data + 16B pad)
#define ARR   (128*PITCH)  // 10240 B per array
#define NRING 4
#define NKT   (GK/32)      // 32 k-tiles

struct GArgs {
  const __half* A;
  const __half* Bh;
  const __half* Bl;
  const float* bias;
  float* C;
  int N;
  int sig;
};

template<int TWO>
__device__ __forceinline__ void gemm_load_stage(uint32_t sbase,
    const __half* A, const __half* Bh, const __half* Bl,
    int kt, int tid)
{
  const int koff = kt * 32;
  #pragma unroll
  for (int it = 0; it < 2; it++){
    const int w = tid + it * 256;      // 0..511
    const int row = w >> 2, c16 = w & 3;
    cp16(sbase + row*PITCH + c16*16,         A  + (size_t)row * GK + koff + c16*8);
    cp16(sbase + ARR + row*PITCH + c16*16,   Bh + (size_t)row * GK + koff + c16*8);
    if (TWO)
      cp16(sbase + 2*ARR + row*PITCH + c16*16, Bl + (size_t)row * GK + koff + c16*8);
  }
}

template<int TWO>
__global__ void __launch_bounds__(256, 1)
hmma_gemm_dual(GArgs g0, GArgs g1, int split)
{
  constexpr int STAGE = (TWO ? 3 : 2) * ARR;
  extern __shared__ __align__(128) char sm[];
  const uint32_t sb = smem_u32(sm);
  const int tid = threadIdx.x;
  const int wid = tid >> 5, lane = tid & 31;
  const int wm = wid & 1, wn = wid >> 1;
  const int m0w = wm * 64, n0w = wn * 32;

  const bool first = ((int)blockIdx.x < split);
  const GArgs ga = first ? g0 : g1;
  const int bxn = first ? (int)blockIdx.x : (int)blockIdx.x - split;
  const int bn0 = bxn << 7, bm0 = blockIdx.y << 7;

  const __half* pA  = ga.A  + (size_t)bm0 * GK;
  const __half* pBh = ga.Bh + (size_t)bn0 * GK;
  const __half* pBl = TWO ? (ga.Bl + (size_t)bn0 * GK) : pBh;

  float acc[4][4][4], accc[4][4][4];
  #pragma unroll
  for (int i = 0; i < 4; i++)
    #pragma unroll
    for (int j = 0; j < 4; j++)
      #pragma unroll
      for (int q = 0; q < 4; q++){ acc[i][j][q] = 0.f; accc[i][j][q] = 0.f; }

  // ldmatrix per-lane offsets
  const int rowA = lane & 15;
  const uint32_t colA = (lane >> 4) << 4;                 // 0 or 16 bytes
  const int rowB = (lane & 7) + (((lane >> 4) & 1) << 3); // 0..15
  const uint32_t colB = ((lane >> 3) & 1) << 4;           // 0 or 16 bytes

  gemm_load_stage<TWO>(sb + 0*STAGE, pA, pBh, pBl, 0, tid); cp_commit();
  gemm_load_stage<TWO>(sb + 1*STAGE, pA, pBh, pBl, 1, tid); cp_commit();
  gemm_load_stage<TWO>(sb + 2*STAGE, pA, pBh, pBl, 2, tid); cp_commit();

  for (int kt = 0; kt < NKT; kt++){
    cp_wait<2>();
    __syncthreads();

    if (kt + 3 < NKT)
      gemm_load_stage<TWO>(sb + ((kt + 3) & (NRING-1)) * STAGE, pA, pBh, pBl, kt + 3, tid);
    cp_commit();

    const uint32_t st = sb + (kt & (NRING-1)) * STAGE;
    const uint32_t aB  = st          + (m0w + rowA) * PITCH + colA;
    const uint32_t bhB = st + ARR    + (n0w + rowB) * PITCH + colB;
    const uint32_t blB = st + 2*ARR  + (n0w + rowB) * PITCH + colB;

    #pragma unroll
    for (int ks = 0; ks < 2; ks++){
      const uint32_t kb = ks * 32;
      uint32_t a16[4][4], bh16[4][2], bl16[4][2];
      #pragma unroll
      for (int mi = 0; mi < 4; mi++)
        ldsm_x4(a16[mi], aB + mi*16*PITCH + kb);
      #pragma unroll
      for (int p = 0; p < 2; p++){
        uint32_t r[4];
        ldsm_x4(r, bhB + p*16*PITCH + kb);
        bh16[2*p][0] = r[0]; bh16[2*p][1] = r[1];
        bh16[2*p+1][0] = r[2]; bh16[2*p+1][1] = r[3];
        if (TWO){
          ldsm_x4(r, blB + p*16*PITCH + kb);
          bl16[2*p][0] = r[0]; bl16[2*p][1] = r[1];
          bl16[2*p+1][0] = r[2]; bl16[2*p+1][1] = r[3];
        }
      }
      #pragma unroll
      for (int mi = 0; mi < 4; mi++)
        #pragma unroll
        for (int nj = 0; nj < 4; nj++)
          mma_f16(acc[mi][nj], a16[mi], bh16[nj]);
      if (TWO){
        #pragma unroll
        for (int mi = 0; mi < 4; mi++)
          #pragma unroll
          for (int nj = 0; nj < 4; nj++)
            mma_f16(accc[mi][nj], a16[mi], bl16[nj]);
      }
    }
  }

  // epilogue
  const int g = lane >> 2, t4 = lane & 3;
  #pragma unroll
  for (int mi = 0; mi < 4; mi++){
    #pragma unroll
    for (int nj = 0; nj < 4; nj++){
      const int row = bm0 + m0w + mi*16 + g;
      const int col = bn0 + n0w + nj*8 + t4*2;
      float b0 = ga.bias[col], b1 = ga.bias[col+1];
      float o0 = acc[mi][nj][0] + b0;
      float o1 = acc[mi][nj][1] + b1;
      float o2 = acc[mi][nj][2] + b0;
      float o3 = acc[mi][nj][3] + b1;
      if (TWO){
        o0 += accc[mi][nj][0] * INV_LO_SCALE;
        o1 += accc[mi][nj][1] * INV_LO_SCALE;
        o2 += accc[mi][nj][2] * INV_LO_SCALE;
        o3 += accc[mi][nj][3] * INV_LO_SCALE;
      }
      if (ga.sig){
        o0 = 1.f / (1.f + expf(-o0)); o1 = 1.f / (1.f + expf(-o1));
        o2 = 1.f / (1.f + expf(-o2)); o3 = 1.f / (1.f + expf(-o3));
      }
      *(float2*)(ga.C + (size_t)row * ga.N + col)       = make_float2(o0, o1);
      *(float2*)(ga.C + (size_t)(row + 8) * ga.N + col) = make_float2(o2, o3);
    }
  }
}

// ---------------- gate-normalize + apply + elu+1 + head split ----------------
__global__ void prep_kernel(const float* __restrict__ gate, const float* __restrict__ qkv,
                            float* __restrict__ Q, float* __restrict__ K, float* __restrict__ V)
{
  __shared__ float red[8];
  const int t = blockIdx.x, i = threadIdx.x;
  float4 gv = ((const float4*)(gate + (size_t)t*D))[i];
  float s = gv.x + gv.y + gv.z + gv.w;
  const int lane = i & 31, w = i >> 5;
  #pragma unroll
  for (int o = 16; o; o >>= 1) s += __shfl_xor_sync(0xffffffffu, s, o);
  if (lane == 0) red[w] = s;
  __syncthreads();
  if (i == 0){
    float a = 0.f;
    #pragma unroll
    for (int k = 0; k < 8; k++) a += red[k];
    red[0] = a;
  }
  __syncthreads();
  const float inv = 1.f / (red[0] * (1.f / D) + 1e-5f);

  const float4* qrow = (const float4*)(qkv + (size_t)t * 3 * D);
  float4 qv = qrow[i], kv = qrow[i + 256], vv = qrow[i + 512];
  float4 qo, ko;
  qo.x = elu1f(qv.x * gv.x * inv); qo.y = elu1f(qv.y * gv.y * inv);
  qo.z = elu1f(qv.z * gv.z * inv); qo.w = elu1f(qv.w * gv.w * inv);
  ko.x = elu1f(kv.x * gv.x * inv); ko.y = elu1f(kv.y * gv.y * inv);
  ko.z = elu1f(kv.z * gv.z * inv); ko.w = elu1f(kv.w * gv.w * inv);

  const int h = i >> 4;
  const int dh = (i & 15) << 2;
  const size_t b4 = ((size_t)(h * T + t) * DH + dh) >> 2;
  ((float4*)Q)[b4] = qo;
  ((float4*)K)[b4] = ko;
  ((float4*)V)[b4] = vv;
}

// ---------------- per-(head,chunk) local K^T V and K column sums ----------------
__global__ void chunk_sums_kernel(const float* __restrict__ Kg, const float* __restrict__ Vg,
                                  float* __restrict__ lkv, float* __restrict__ lks)
{
  extern __shared__ float smf[];
  float* Ks = smf;
  float* Vs = smf + CS * DH;
  const int hc = blockIdx.x, h = hc >> 4, c = hc & 15;
  const float* Kc = Kg + (size_t)(h * T + c * CS) * DH;
  const float* Vc = Vg + (size_t)(h * T + c * CS) * DH;
  const int tid = threadIdx.x;
  for (int idx = tid; idx < CS * DH / 4; idx += 256){
    ((float4*)Ks)[idx] = ((const float4*)Kc)[idx];
    ((float4*)Vs)[idx] = ((const float4*)Vc)[idx];
  }
  __syncthreads();

  const int m = tid & 63;
  const int dg = tid >> 6;
  float acc[16];
  #pragma unroll
  for (int i = 0; i < 16; i++) acc[i] = 0.f;
  for (int tt = 0; tt < CS; tt++){
    const float vv = Vs[tt * DH + m];
    #pragma unroll
    for (int i = 0; i < 16; i++)
      acc[i] += Ks[tt * DH + dg * 16 + i] * vv;
  }
  float* dst = lkv + (size_t)hc * DH * DH;
  #pragma unroll
  for (int i = 0; i < 16; i++)
    dst[(dg * 16 + i) * DH + m] = acc[i];

  if (tid < DH){
    float s = 0.f;
    for (int tt = 0; tt < CS; tt++) s += Ks[tt * DH + tid];
    lks[(size_t)hc * DH + tid] = s;
  }
}

// ---------------- exclusive prefix over chunks ----------------
__global__ void scan_kernel(const float* __restrict__ lkv, const float* __restrict__ lks,
                            float* __restrict__ Spre, float* __restrict__ zpre)
{
  const int h = blockIdx.x;
  for (int idx = threadIdx.x; idx < DH * DH; idx += blockDim.x){
    float acc = 0.f;
    for (int c = 0; c < NC; c++){
      const size_t o = (size_t)(h * NC + c) * DH * DH + idx;
      Spre[o] = acc;
      acc += lkv[o];
    }
  }
  for (int idx = threadIdx.x; idx < DH; idx += blockDim.x){
    float acc = 0.f;
    for (int c = 0; c < NC; c++){
      const size_t o = (size_t)(h * NC + c) * DH + idx;
      zpre[o] = acc;
      acc += lks[o];
    }
  }
}

// ---------------- per-(head,chunk) attention output -> fp16 ----------------
__global__ void attn_kernel(const float* __restrict__ Qg, const float* __restrict__ Kg,
                            const float* __restrict__ Vg, const float* __restrict__ Spre,
                            const float* __restrict__ zpre)
{
  extern __shared__ float smf[];
  float* Qs  = smf;              // 128 x 65
  float* Ks  = Qs  + 128 * 65;   // 128 x 65 (later reused for V)
  float* As  = Ks  + 128 * 65;   // 128 x 130
  float* Sp  = As  + 128 * 130;  // 64 x 65
  float* zp  = Sp  + 64 * 65;    // 64
  float* dn  = zp  + 64;         // 128
  float* dnp = dn  + 128;        // 128 x 16

  const int hc = blockIdx.x, h = hc >> 4, c = hc & 15;
  const int tid = threadIdx.x;
  const float* Qc = Qg + (size_t)(h * T + c * CS) * DH;
  const float* Kc = Kg + (size_t)(h * T + c * CS) * DH;

  for (int idx = tid; idx < CS * DH / 4; idx += 256){
    const int r = idx >> 4, c4 = (idx & 15) << 2;
    float4 q = ((const float4*)Qc)[idx];
    float4 k = ((const float4*)Kc)[idx];
    float* qd = Qs + r * 65 + c4;
    qd[0] = q.x; qd[1] = q.y; qd[2] = q.z; qd[3] = q.w;
    float* kd = Ks + r * 65 + c4;
    kd[0] = k.x; kd[1] = k.y; kd[2] = k.z; kd[3] = k.w;
  }
  const float* SpG = Spre + (size_t)hc * DH * DH;
  for (int idx = tid; idx < DH * DH; idx += 256)
    Sp[(idx >> 6) * 65 + (idx & 63)] = SpG[idx];
  if (tid < 64) zp[tid] = zpre[(size_t)hc * DH + tid];
  __syncthreads();

  if (tid < 128){
    float s = 0.f;
    #pragma unroll
    for (int d = 0; d < 64; d++) s += Qs[tid * 65 + d] * zp[d];
    dn[tid] = s;
  }
  __syncthreads();

  const int tx = tid & 15, ty = tid >> 4;
  {
    float acc[8][8];
    #pragma unroll
    for (int i = 0; i < 8; i++)
      #pragma unroll
      for (int j = 0; j < 8; j++) acc[i][j] = 0.f;
    for (int d = 0; d < 64; d++){
      float a[8], b[8];
      #pragma unroll
      for (int i = 0; i < 8; i++) a[i] = Qs[(ty * 8 + i) * 65 + d];
      #pragma unroll
      for (int j = 0; j < 8; j++) b[j] = Ks[(tx * 8 + j) * 65 + d];
      #pragma unroll
      for (int i = 0; i < 8; i++)
        #pragma unroll
        for (int j = 0; j < 8; j++)
          acc[i][j] += a[i] * b[j];
    }
    #pragma unroll
    for (int i = 0; i < 8; i++){
      const int r = ty * 8 + i;
      float rs = 0.f;
      #pragma unroll
      for (int j = 0; j < 8; j++){
        const int s_ = tx * 8 + j;
        const float v = (s_ <= r) ? acc[i][j] : 0.f;
        As[r * 130 + s_] = v;
        rs += v;
      }
      dnp[r * 16 + tx] = rs;
    }
  }
  __syncthreads();

  {
    const float* Vc = Vg + (size_t)(h * T + c * CS) * DH;
    for (int idx = tid; idx < CS * DH / 4; idx += 256){
      const int r = idx >> 4, c4 = (idx & 15) << 2;
      float4 v = ((const float4*)Vc)[idx];
      float* vd = Ks + r * 65 + c4;
      vd[0] = v.x; vd[1] = v.y; vd[2] = v.z; vd[3] = v.w;
    }
    if (tid < 128){
      float s = dn[tid];
      #pragma unroll
      for (int xx = 0; xx < 16; xx++) s += dnp[tid * 16 + xx];
      dn[tid] = s + 1e-5f;
    }
  }
  __syncthreads();

  {
    float acc2[8][4];
    #pragma unroll
    for (int i = 0; i < 8; i++)
      #pragma unroll
      for (int j = 0; j < 4; j++) acc2[i][j] = 0.f;
    const int m0 = tx * 4, r0 = ty * 8;
    for (int s = 0; s < 128; s++){
      float vv[4];
      #pragma unroll
      for (int jj = 0; jj < 4; jj++) vv[jj] = Ks[s * 65 + m0 + jj];
      #pragma unroll
      for (int i = 0; i < 8; i++){
        const float av = As[(r0 + i) * 130 + s];
        #pragma unroll
        for (int jj = 0; jj < 4; jj++) acc2[i][jj] += av * vv[jj];
      }
    }
    for (int d = 0; d < 64; d++){
      float sp[4];
      #pragma unroll
      for (int jj = 0; jj < 4; jj++) sp[jj] = Sp[d * 65 + m0 + jj];
      #pragma unroll
      for (int i = 0; i < 8; i++){
        const float qv = Qs[(r0 + i) * 65 + d];
        #pragma unroll
        for (int jj = 0; jj < 4; jj++) acc2[i][jj] += qv * sp[jj];
      }
    }
    const size_t obase = (size_t)(c * CS) * D + h * DH;
    #pragma unroll
    for (int i = 0; i < 8; i++){
      const float inv = 1.f / dn[r0 + i];
      const size_t ptr = obase + (size_t)(r0 + i) * D + m0;
      *(__half2*)&g_aa[ptr]     = __floats2half2_rn(acc2[i][0] * inv, acc2[i][1] * inv);
      *(__half2*)&g_aa[ptr + 2] = __floats2half2_rn(acc2[i][2] * inv, acc2[i][3] * inv);
    }
  }
}

// ---------------- launch ----------------
extern "C" void kernel_launch(void* const* d_in, const int* in_sizes, int n_in,
                              void* d_out, int out_size)
{
  (void)in_sizes; (void)n_in; (void)out_size;
  const float* x      = (const float*)d_in[0];
  const float* ln_g   = (const float*)d_in[1];
  const float* ln_b   = (const float*)d_in[2];
  const float* qkv_w  = (const float*)d_in[3];
  const float* qkv_b  = (const float*)d_in[4];
  const float* gate_w = (const float*)d_in[5];
  const float* gate_b = (const float*)d_in[6];
  const float* proj_w = (const float*)d_in[7];
  const float* proj_b = (const float*)d_in[8];
  float* out = (float*)d_out;

  float *gate, *qkv, *Q, *K, *V, *lkv, *lks, *Spre, *zpre;
  __half *xa, *xna, *aa, *qwh, *gwh, *pwh, *pwl;
  cudaGetSymbolAddress((void**)&gate, g_gate);
  cudaGetSymbolAddress((void**)&qkv,  g_qkv);
  cudaGetSymbolAddress((void**)&Q,    g_Q);
  cudaGetSymbolAddress((void**)&K,    g_K);
  cudaGetSymbolAddress((void**)&V,    g_V);
  cudaGetSymbolAddress((void**)&lkv,  g_lkv);
  cudaGetSymbolAddress((void**)&lks,  g_lks);
  cudaGetSymbolAddress((void**)&Spre, g_Spre);
  cudaGetSymbolAddress((void**)&zpre, g_zpre);
  cudaGetSymbolAddress((void**)&xa,   g_xa);
  cudaGetSymbolAddress((void**)&xna,  g_xna);
  cudaGetSymbolAddress((void**)&aa,   g_aa);
  cudaGetSymbolAddress((void**)&qwh,  g_qwh);
  cudaGetSymbolAddress((void**)&gwh,  g_gwh);
  cudaGetSymbolAddress((void**)&pwh,  g_pwh);
  cudaGetSymbolAddress((void**)&pwl,  g_pwl);

  const int CHUNK_SMEM = 2 * CS * DH * 4;
  const int ATTN_SMEM  = (128*65 + 128*65 + 128*130 + 64*65 + 64 + 128 + 128*16) * 4;
  const int GEMM_SMEM1 = NRING * 2 * ARR;  // 81920
  const int GEMM_SMEM2 = NRING * 3 * ARR;  // 122880
  cudaFuncSetAttribute(chunk_sums_kernel, cudaFuncAttributeMaxDynamicSharedMemorySize, CHUNK_SMEM);
  cudaFuncSetAttribute(attn_kernel,       cudaFuncAttributeMaxDynamicSharedMemorySize, ATTN_SMEM);
  cudaFuncSetAttribute(hmma_gemm_dual<0>, cudaFuncAttributeMaxDynamicSharedMemorySize, GEMM_SMEM1);
  cudaFuncSetAttribute(hmma_gemm_dual<1>, cudaFuncAttributeMaxDynamicSharedMemorySize, GEMM_SMEM2);

  split_all_kernel<<<(X4 + Q4 + G4 + P4) / 256, 256>>>(x, qkv_w, gate_w, proj_w);
  ln_kernel<<<T, 256>>>(x, ln_g, ln_b);

  // gate + qkv single-term fp16 (merged launch)
  GArgs gateArgs = { xa,  gwh, nullptr, gate_b, gate, D,     1 };
  GArgs qkvArgs  = { xna, qwh, nullptr, qkv_b,  qkv,  3 * D, 0 };
  hmma_gemm_dual<0><<<dim3(8 + 24, T / 128), 256, GEMM_SMEM1>>>(gateArgs, qkvArgs, 8);

  prep_kernel<<<T, 256>>>(gate, qkv, Q, K, V);
  chunk_sums_kernel<<<H * NC, 256, CHUNK_SMEM>>>(K, V, lkv, lks);
  scan_kernel<<<H, 256>>>(lkv, lks, Spre, zpre);
  attn_kernel<<<H * NC, 256, ATTN_SMEM>>>(Q, K, V, Spre, zpre);

  // proj: 2-term (directly in output; keep the correction)
  GArgs projArgs = { aa, pwh, pwl, proj_b, out, D, 0 };
  hmma_gemm_dual<1><<<dim3(8, T / 128), 256, GEMM_SMEM2>>>(projArgs, projArgs, 8);
}

// round 9
// speedup vs baseline: 1.9488x; 1.1547x over previous
#include <cuda_runtime.h>
#include <cuda_fp16.h>
#include <cstdint>
#include <math.h>

#define T 2048
#define D 1024
#define H 16
#define DH 64
#define NC 16
#define CS 128
#define GK 1024

// ---------------- scratch (no allocations allowed) ----------------
__device__ float g_gate[T*D];
__device__ float g_qkv[T*3*D];
__device__ float g_Q[T*D];
__device__ float g_K[T*D];
__device__ float g_V[T*D];
__device__ float g_lkv[H*NC*DH*DH];
__device__ float g_lks[H*NC*DH];
__device__ float g_Spre[H*NC*DH*DH];
__device__ float g_zpre[H*NC*DH];

// fp16 activations and weights (single-rounded)
__device__ __half g_xa[T*D];          // fp16(x)
__device__ __half g_xna[T*D];         // fp16(ln(x))
__device__ __half g_aa[T*D];          // fp16(attn out)
__device__ __half g_qwh[3*D*D];
__device__ __half g_gwh[D*D];
__device__ __half g_pwh[D*D];

// ---------------- helpers ----------------
__device__ __forceinline__ uint32_t smem_u32(const void* p){
  uint32_t a;
  asm("{ .reg .u64 t; cvta.to.shared.u64 t, %1; cvt.u32.u64 %0, t; }" : "=r"(a) : "l"(p));
  return a;
}
__device__ __forceinline__ float elu1f(float x){ return x > 0.f ? x + 1.f : expf(x); }

__device__ __forceinline__ void ldsm_x4(uint32_t* r, uint32_t addr){
  asm volatile("ldmatrix.sync.aligned.m8n8.x4.shared.b16 {%0,%1,%2,%3}, [%4];"
    : "=r"(r[0]), "=r"(r[1]), "=r"(r[2]), "=r"(r[3]) : "r"(addr));
}
__device__ __forceinline__ void mma_f16(float* c, const uint32_t* a, const uint32_t* b){
  asm volatile(
    "mma.sync.aligned.m16n8k16.row.col.f32.f16.f16.f32 "
    "{%0,%1,%2,%3},{%4,%5,%6,%7},{%8,%9},{%0,%1,%2,%3};"
    : "+f"(c[0]), "+f"(c[1]), "+f"(c[2]), "+f"(c[3])
    : "r"(a[0]), "r"(a[1]), "r"(a[2]), "r"(a[3]), "r"(b[0]), "r"(b[1]));
}
__device__ __forceinline__ void cp16(uint32_t smem, const void* gmem){
  asm volatile("cp.async.cg.shared.global [%0], [%1], 16;" :: "r"(smem), "l"(gmem));
}
__device__ __forceinline__ void cp_commit(){
  asm volatile("cp.async.commit_group;" ::: "memory");
}
template<int N>
__device__ __forceinline__ void cp_wait(){
  asm volatile("cp.async.wait_group %0;" :: "n"(N) : "memory");
}

// ---------------- fused split(+LN) kernel ----------------
// blocks [0, NB_SPLIT): fp32 -> fp16 conversions for x, qkv_w, gate_w, proj_w
// blocks [NB_SPLIT, NB_SPLIT+T): LayerNorm rows -> fp16
#define X4 (T*D/4)
#define Q4 (3*D*D/4)
#define G4 (D*D/4)
#define P4 (D*D/4)
#define NB_SPLIT ((X4 + Q4 + G4 + P4) / 256)
__global__ void split_ln_kernel(const float* __restrict__ x, const float* __restrict__ qw,
                                const float* __restrict__ gw, const float* __restrict__ pw,
                                const float* __restrict__ ln_g, const float* __restrict__ ln_b)
{
  if ((int)blockIdx.x < NB_SPLIT){
    int i = blockIdx.x * 256 + threadIdx.x;
    const float* src; __half* hp; int j;
    if (i < X4){ src = x; hp = g_xa; j = i; }
    else if (i < X4 + Q4){ src = qw; hp = g_qwh; j = i - X4; }
    else if (i < X4 + Q4 + G4){ src = gw; hp = g_gwh; j = i - (X4 + Q4); }
    else { src = pw; hp = g_pwh; j = i - (X4 + Q4 + G4); }
    float4 v = ((const float4*)src)[j];
    ((__half2*)hp)[j*2]   = __floats2half2_rn(v.x, v.y);
    ((__half2*)hp)[j*2+1] = __floats2half2_rn(v.z, v.w);
    return;
  }
  // LayerNorm path
  __shared__ float red[16];
  const int t = blockIdx.x - NB_SPLIT;
  const int i = threadIdx.x;
  float4 xv = ((const float4*)(x + (size_t)t*D))[i];
  float s  = xv.x + xv.y + xv.z + xv.w;
  float s2 = xv.x*xv.x + xv.y*xv.y + xv.z*xv.z + xv.w*xv.w;
  const int lane = i & 31, w = i >> 5;
  #pragma unroll
  for (int o = 16; o; o >>= 1){
    s  += __shfl_xor_sync(0xffffffffu, s,  o);
    s2 += __shfl_xor_sync(0xffffffffu, s2, o);
  }
  if (lane == 0){ red[w] = s; red[8+w] = s2; }
  __syncthreads();
  if (i == 0){
    float a = 0.f, c = 0.f;
    #pragma unroll
    for (int k = 0; k < 8; k++){ a += red[k]; c += red[8+k]; }
    red[0] = a; red[8] = c;
  }
  __syncthreads();
  const float mu   = red[0] * (1.f / D);
  const float var  = red[8] * (1.f / D) - mu * mu;
  const float rstd = rsqrtf(var + 1e-5f);
  float4 gv = ((const float4*)ln_g)[i];
  float4 bv = ((const float4*)ln_b)[i];
  float o0 = (xv.x - mu) * rstd * gv.x + bv.x;
  float o1 = (xv.y - mu) * rstd * gv.y + bv.y;
  float o2 = (xv.z - mu) * rstd * gv.z + bv.z;
  float o3 = (xv.w - mu) * rstd * gv.w + bv.w;
  const size_t idx4 = ((size_t)t*D >> 2) + i;
  ((__half2*)g_xna)[idx4*2]   = __floats2half2_rn(o0, o1);
  ((__half2*)g_xna)[idx4*2+1] = __floats2half2_rn(o2, o3);
}

// ---------------- HMMA GEMM: C[2048,N] = A[2048,1024] @ B[N,1024]^T ----------------
// single fp16 term: C = A·B + bias (optional sigmoid)
// Block tile 128x128, BK=32, 8 warps of 64x32, 4-stage cp.async ring, 2 CTAs/SM.
#define PITCH 80           // bytes per SMEM row (64B data + 16B pad)
#define ARR   (128*PITCH)  // 10240 B per array
#define STAGE (2*ARR)      // A + B = 20480 B
#define NRING 4
#define NKT   (GK/32)      // 32 k-tiles
#define GEMM_SMEM (NRING*STAGE)  // 81920 B

struct GArgs {
  const __half* A;
  const __half* B;
  const float* bias;
  float* C;
  int N;
  int sig;
};

__device__ __forceinline__ void gemm_load_stage(uint32_t sbase,
    const __half* A, const __half* B, int kt, int tid)
{
  const int koff = kt * 32;
  #pragma unroll
  for (int it = 0; it < 2; it++){
    const int w = tid + it * 256;      // 0..511
    const int row = w >> 2, c16 = w & 3;
    cp16(sbase + row*PITCH + c16*16,       A + (size_t)row * GK + koff + c16*8);
    cp16(sbase + ARR + row*PITCH + c16*16, B + (size_t)row * GK + koff + c16*8);
  }
}

__global__ void __launch_bounds__(256, 2)
hmma_gemm_dual(GArgs g0, GArgs g1, int split)
{
  extern __shared__ __align__(128) char sm[];
  const uint32_t sb = smem_u32(sm);
  const int tid = threadIdx.x;
  const int wid = tid >> 5, lane = tid & 31;
  const int wm = wid & 1, wn = wid >> 1;
  const int m0w = wm * 64, n0w = wn * 32;

  const bool first = ((int)blockIdx.x < split);
  const GArgs ga = first ? g0 : g1;
  const int bxn = first ? (int)blockIdx.x : (int)blockIdx.x - split;
  const int bn0 = bxn << 7, bm0 = blockIdx.y << 7;

  const __half* pA = ga.A + (size_t)bm0 * GK;
  const __half* pB = ga.B + (size_t)bn0 * GK;

  float acc[4][4][4];
  #pragma unroll
  for (int i = 0; i < 4; i++)
    #pragma unroll
    for (int j = 0; j < 4; j++)
      #pragma unroll
      for (int q = 0; q < 4; q++) acc[i][j][q] = 0.f;

  // ldmatrix per-lane offsets
  const int rowA = lane & 15;
  const uint32_t colA = (lane >> 4) << 4;                 // 0 or 16 bytes
  const int rowB = (lane & 7) + (((lane >> 4) & 1) << 3); // 0..15
  const uint32_t colB = ((lane >> 3) & 1) << 4;           // 0 or 16 bytes

  gemm_load_stage(sb + 0*STAGE, pA, pB, 0, tid); cp_commit();
  gemm_load_stage(sb + 1*STAGE, pA, pB, 1, tid); cp_commit();
  gemm_load_stage(sb + 2*STAGE, pA, pB, 2, tid); cp_commit();

  for (int kt = 0; kt < NKT; kt++){
    cp_wait<2>();
    __syncthreads();

    if (kt + 3 < NKT)
      gemm_load_stage(sb + ((kt + 3) & (NRING-1)) * STAGE, pA, pB, kt + 3, tid);
    cp_commit();

    const uint32_t st = sb + (kt & (NRING-1)) * STAGE;
    const uint32_t aB = st       + (m0w + rowA) * PITCH + colA;
    const uint32_t bB = st + ARR + (n0w + rowB) * PITCH + colB;

    #pragma unroll
    for (int ks = 0; ks < 2; ks++){
      const uint32_t kb = ks * 32;
      uint32_t a16[4][4], b16[4][2];
      #pragma unroll
      for (int mi = 0; mi < 4; mi++)
        ldsm_x4(a16[mi], aB + mi*16*PITCH + kb);
      #pragma unroll
      for (int p = 0; p < 2; p++){
        uint32_t r[4];
        ldsm_x4(r, bB + p*16*PITCH + kb);
        b16[2*p][0] = r[0]; b16[2*p][1] = r[1];
        b16[2*p+1][0] = r[2]; b16[2*p+1][1] = r[3];
      }
      #pragma unroll
      for (int mi = 0; mi < 4; mi++)
        #pragma unroll
        for (int nj = 0; nj < 4; nj++)
          mma_f16(acc[mi][nj], a16[mi], b16[nj]);
    }
  }

  // epilogue
  const int g = lane >> 2, t4 = lane & 3;
  #pragma unroll
  for (int mi = 0; mi < 4; mi++){
    #pragma unroll
    for (int nj = 0; nj < 4; nj++){
      const int row = bm0 + m0w + mi*16 + g;
      const int col = bn0 + n0w + nj*8 + t4*2;
      float b0 = ga.bias[col], b1 = ga.bias[col+1];
      float o0 = acc[mi][nj][0] + b0;
      float o1 = acc[mi][nj][1] + b1;
      float o2 = acc[mi][nj][2] + b0;
      float o3 = acc[mi][nj][3] + b1;
      if (ga.sig){
        o0 = 1.f / (1.f + expf(-o0)); o1 = 1.f / (1.f + expf(-o1));
        o2 = 1.f / (1.f + expf(-o2)); o3 = 1.f / (1.f + expf(-o3));
      }
      *(float2*)(ga.C + (size_t)row * ga.N + col)       = make_float2(o0, o1);
      *(float2*)(ga.C + (size_t)(row + 8) * ga.N + col) = make_float2(o2, o3);
    }
  }
}

// ---------------- gate-normalize + apply + elu+1 + head split ----------------
__global__ void prep_kernel(const float* __restrict__ gate, const float* __restrict__ qkv,
                            float* __restrict__ Q, float* __restrict__ K, float* __restrict__ V)
{
  __shared__ float red[8];
  const int t = blockIdx.x, i = threadIdx.x;
  float4 gv = ((const float4*)(gate + (size_t)t*D))[i];
  float s = gv.x + gv.y + gv.z + gv.w;
  const int lane = i & 31, w = i >> 5;
  #pragma unroll
  for (int o = 16; o; o >>= 1) s += __shfl_xor_sync(0xffffffffu, s, o);
  if (lane == 0) red[w] = s;
  __syncthreads();
  if (i == 0){
    float a = 0.f;
    #pragma unroll
    for (int k = 0; k < 8; k++) a += red[k];
    red[0] = a;
  }
  __syncthreads();
  const float inv = 1.f / (red[0] * (1.f / D) + 1e-5f);

  const float4* qrow = (const float4*)(qkv + (size_t)t * 3 * D);
  float4 qv = qrow[i], kv = qrow[i + 256], vv = qrow[i + 512];
  float4 qo, ko;
  qo.x = elu1f(qv.x * gv.x * inv); qo.y = elu1f(qv.y * gv.y * inv);
  qo.z = elu1f(qv.z * gv.z * inv); qo.w = elu1f(qv.w * gv.w * inv);
  ko.x = elu1f(kv.x * gv.x * inv); ko.y = elu1f(kv.y * gv.y * inv);
  ko.z = elu1f(kv.z * gv.z * inv); ko.w = elu1f(kv.w * gv.w * inv);

  const int h = i >> 4;
  const int dh = (i & 15) << 2;
  const size_t b4 = ((size_t)(h * T + t) * DH + dh) >> 2;
  ((float4*)Q)[b4] = qo;
  ((float4*)K)[b4] = ko;
  ((float4*)V)[b4] = vv;
}

// ---------------- per-(head,chunk) local K^T V and K column sums ----------------
__global__ void chunk_sums_kernel(const float* __restrict__ Kg, const float* __restrict__ Vg,
                                  float* __restrict__ lkv, float* __restrict__ lks)
{
  extern __shared__ float smf[];
  float* Ks = smf;
  float* Vs = smf + CS * DH;
  const int hc = blockIdx.x, h = hc >> 4, c = hc & 15;
  const float* Kc = Kg + (size_t)(h * T + c * CS) * DH;
  const float* Vc = Vg + (size_t)(h * T + c * CS) * DH;
  const int tid = threadIdx.x;
  for (int idx = tid; idx < CS * DH / 4; idx += 256){
    ((float4*)Ks)[idx] = ((const float4*)Kc)[idx];
    ((float4*)Vs)[idx] = ((const float4*)Vc)[idx];
  }
  __syncthreads();

  const int m = tid & 63;
  const int dg = tid >> 6;
  float acc[16];
  #pragma unroll
  for (int i = 0; i < 16; i++) acc[i] = 0.f;
  for (int tt = 0; tt < CS; tt++){
    const float vv = Vs[tt * DH + m];
    #pragma unroll
    for (int i = 0; i < 16; i++)
      acc[i] += Ks[tt * DH + dg * 16 + i] * vv;
  }
  float* dst = lkv + (size_t)hc * DH * DH;
  #pragma unroll
  for (int i = 0; i < 16; i++)
    dst[(dg * 16 + i) * DH + m] = acc[i];

  if (tid < DH){
    float s = 0.f;
    for (int tt = 0; tt < CS; tt++) s += Ks[tt * DH + tid];
    lks[(size_t)hc * DH + tid] = s;
  }
}

// ---------------- exclusive prefix over chunks ----------------
__global__ void scan_kernel(const float* __restrict__ lkv, const float* __restrict__ lks,
                            float* __restrict__ Spre, float* __restrict__ zpre)
{
  const int h = blockIdx.x;
  for (int idx = threadIdx.x; idx < DH * DH; idx += blockDim.x){
    float acc = 0.f;
    for (int c = 0; c < NC; c++){
      const size_t o = (size_t)(h * NC + c) * DH * DH + idx;
      Spre[o] = acc;
      acc += lkv[o];
    }
  }
  for (int idx = threadIdx.x; idx < DH; idx += blockDim.x){
    float acc = 0.f;
    for (int c = 0; c < NC; c++){
      const size_t o = (size_t)(h * NC + c) * DH + idx;
      zpre[o] = acc;
      acc += lks[o];
    }
  }
}

// ---------------- per-(head,chunk) attention output -> fp16 ----------------
__global__ void attn_kernel(const float* __restrict__ Qg, const float* __restrict__ Kg,
                            const float* __restrict__ Vg, const float* __restrict__ Spre,
                            const float* __restrict__ zpre)
{
  extern __shared__ float smf[];
  float* Qs  = smf;              // 128 x 65
  float* Ks  = Qs  + 128 * 65;   // 128 x 65 (later reused for V)
  float* As  = Ks  + 128 * 65;   // 128 x 130
  float* Sp  = As  + 128 * 130;  // 64 x 65
  float* zp  = Sp  + 64 * 65;    // 64
  float* dn  = zp  + 64;         // 128
  float* dnp = dn  + 128;        // 128 x 16

  const int hc = blockIdx.x, h = hc >> 4, c = hc & 15;
  const int tid = threadIdx.x;
  const float* Qc = Qg + (size_t)(h * T + c * CS) * DH;
  const float* Kc = Kg + (size_t)(h * T + c * CS) * DH;

  for (int idx = tid; idx < CS * DH / 4; idx += 256){
    const int r = idx >> 4, c4 = (idx & 15) << 2;
    float4 q = ((const float4*)Qc)[idx];
    float4 k = ((const float4*)Kc)[idx];
    float* qd = Qs + r * 65 + c4;
    qd[0] = q.x; qd[1] = q.y; qd[2] = q.z; qd[3] = q.w;
    float* kd = Ks + r * 65 + c4;
    kd[0] = k.x; kd[1] = k.y; kd[2] = k.z; kd[3] = k.w;
  }
  const float* SpG = Spre + (size_t)hc * DH * DH;
  for (int idx = tid; idx < DH * DH; idx += 256)
    Sp[(idx >> 6) * 65 + (idx & 63)] = SpG[idx];
  if (tid < 64) zp[tid] = zpre[(size_t)hc * DH + tid];
  __syncthreads();

  if (tid < 128){
    float s = 0.f;
    #pragma unroll
    for (int d = 0; d < 64; d++) s += Qs[tid * 65 + d] * zp[d];
    dn[tid] = s;
  }
  __syncthreads();

  const int tx = tid & 15, ty = tid >> 4;
  {
    float acc[8][8];
    #pragma unroll
    for (int i = 0; i < 8; i++)
      #pragma unroll
      for (int j = 0; j < 8; j++) acc[i][j] = 0.f;
    for (int d = 0; d < 64; d++){
      float a[8], b[8];
      #pragma unroll
      for (int i = 0; i < 8; i++) a[i] = Qs[(ty * 8 + i) * 65 + d];
      #pragma unroll
      for (int j = 0; j < 8; j++) b[j] = Ks[(tx * 8 + j) * 65 + d];
      #pragma unroll
      for (int i = 0; i < 8; i++)
        #pragma unroll
        for (int j = 0; j < 8; j++)
          acc[i][j] += a[i] * b[j];
    }
    #pragma unroll
    for (int i = 0; i < 8; i++){
      const int r = ty * 8 + i;
      float rs = 0.f;
      #pragma unroll
      for (int j = 0; j < 8; j++){
        const int s_ = tx * 8 + j;
        const float v = (s_ <= r) ? acc[i][j] : 0.f;
        As[r * 130 + s_] = v;
        rs += v;
      }
      dnp[r * 16 + tx] = rs;
    }
  }
  __syncthreads();

  {
    const float* Vc = Vg + (size_t)(h * T + c * CS) * DH;
    for (int idx = tid; idx < CS * DH / 4; idx += 256){
      const int r = idx >> 4, c4 = (idx & 15) << 2;
      float4 v = ((const float4*)Vc)[idx];
      float* vd = Ks + r * 65 + c4;
      vd[0] = v.x; vd[1] = v.y; vd[2] = v.z; vd[3] = v.w;
    }
    if (tid < 128){
      float s = dn[tid];
      #pragma unroll
      for (int xx = 0; xx < 16; xx++) s += dnp[tid * 16 + xx];
      dn[tid] = s + 1e-5f;
    }
  }
  __syncthreads();

  {
    float acc2[8][4];
    #pragma unroll
    for (int i = 0; i < 8; i++)
      #pragma unroll
      for (int j = 0; j < 4; j++) acc2[i][j] = 0.f;
    const int m0 = tx * 4, r0 = ty * 8;
    for (int s = 0; s < 128; s++){
      float vv[4];
      #pragma unroll
      for (int jj = 0; jj < 4; jj++) vv[jj] = Ks[s * 65 + m0 + jj];
      #pragma unroll
      for (int i = 0; i < 8; i++){
        const float av = As[(r0 + i) * 130 + s];
        #pragma unroll
        for (int jj = 0; jj < 4; jj++) acc2[i][jj] += av * vv[jj];
      }
    }
    for (int d = 0; d < 64; d++){
      float sp[4];
      #pragma unroll
      for (int jj = 0; jj < 4; jj++) sp[jj] = Sp[d * 65 + m0 + jj];
      #pragma unroll
      for (int i = 0; i < 8; i++){
        const float qv = Qs[(r0 + i) * 65 + d];
        #pragma unroll
        for (int jj = 0; jj < 4; jj++) acc2[i][jj] += qv * sp[jj];
      }
    }
    const size_t obase = (size_t)(c * CS) * D + h * DH;
    #pragma unroll
    for (int i = 0; i < 8; i++){
      const float inv = 1.f / dn[r0 + i];
      const size_t ptr = obase + (size_t)(r0 + i) * D + m0;
      *(__half2*)&g_aa[ptr]     = __floats2half2_rn(acc2[i][0] * inv, acc2[i][1] * inv);
      *(__half2*)&g_aa[ptr + 2] = __floats2half2_rn(acc2[i][2] * inv, acc2[i][3] * inv);
    }
  }
}

// ---------------- launch ----------------
extern "C" void kernel_launch(void* const* d_in, const int* in_sizes, int n_in,
                              void* d_out, int out_size)
{
  (void)in_sizes; (void)n_in; (void)out_size;
  const float* x      = (const float*)d_in[0];
  const float* ln_g   = (const float*)d_in[1];
  const float* ln_b   = (const float*)d_in[2];
  const float* qkv_w  = (const float*)d_in[3];
  const float* qkv_b  = (const float*)d_in[4];
  const float* gate_w = (const float*)d_in[5];
  const float* gate_b = (const float*)d_in[6];
  const float* proj_w = (const float*)d_in[7];
  const float* proj_b = (const float*)d_in[8];
  float* out = (float*)d_out;

  float *gate, *qkv, *Q, *K, *V, *lkv, *lks, *Spre, *zpre;
  __half *xa, *xna, *aa, *qwh, *gwh, *pwh;
  cudaGetSymbolAddress((void**)&gate, g_gate);
  cudaGetSymbolAddress((void**)&qkv,  g_qkv);
  cudaGetSymbolAddress((void**)&Q,    g_Q);
  cudaGetSymbolAddress((void**)&K,    g_K);
  cudaGetSymbolAddress((void**)&V,    g_V);
  cudaGetSymbolAddress((void**)&lkv,  g_lkv);
  cudaGetSymbolAddress((void**)&lks,  g_lks);
  cudaGetSymbolAddress((void**)&Spre, g_Spre);
  cudaGetSymbolAddress((void**)&zpre, g_zpre);
  cudaGetSymbolAddress((void**)&xa,   g_xa);
  cudaGetSymbolAddress((void**)&xna,  g_xna);
  cudaGetSymbolAddress((void**)&aa,   g_aa);
  cudaGetSymbolAddress((void**)&qwh,  g_qwh);
  cudaGetSymbolAddress((void**)&gwh,  g_gwh);
  cudaGetSymbolAddress((void**)&pwh,  g_pwh);

  const int CHUNK_SMEM = 2 * CS * DH * 4;
  const int ATTN_SMEM  = (128*65 + 128*65 + 128*130 + 64*65 + 64 + 128 + 128*16) * 4;
  cudaFuncSetAttribute(chunk_sums_kernel, cudaFuncAttributeMaxDynamicSharedMemorySize, CHUNK_SMEM);
  cudaFuncSetAttribute(attn_kernel,       cudaFuncAttributeMaxDynamicSharedMemorySize, ATTN_SMEM);
  cudaFuncSetAttribute(hmma_gemm_dual,    cudaFuncAttributeMaxDynamicSharedMemorySize, GEMM_SMEM);

  // fused conversions + LayerNorm
  split_ln_kernel<<<NB_SPLIT + T, 256>>>(x, qkv_w, gate_w, proj_w, ln_g, ln_b);

  // gate + qkv single-term fp16 (merged launch)
  GArgs gateArgs = { xa,  gwh, gate_b, gate, D,     1 };
  GArgs qkvArgs  = { xna, qwh, qkv_b,  qkv,  3 * D, 0 };
  hmma_gemm_dual<<<dim3(8 + 24, T / 128), 256, GEMM_SMEM>>>(gateArgs, qkvArgs, 8);

  prep_kernel<<<T, 256>>>(gate, qkv, Q, K, V);
  chunk_sums_kernel<<<H * NC, 256, CHUNK_SMEM>>>(K, V, lkv, lks);
  scan_kernel<<<H, 256>>>(lkv, lks, Spre, zpre);
  attn_kernel<<<H * NC, 256, ATTN_SMEM>>>(Q, K, V, Spre, zpre);

  // proj: single-term fp16
  GArgs projArgs = { aa, pwh, proj_b, out, D, 0 };
  hmma_gemm_dual<<<dim3(8, T / 128), 256, GEMM_SMEM>>>(projArgs, projArgs, 8);
}

// round 10
// speedup vs baseline: 2.0931x; 1.0740x over previous
#include <cuda_runtime.h>
#include <cuda_fp16.h>
#include <cstdint>
#include <math.h>

#define T 2048
#define D 1024
#define H 16
#define DH 64
#define NC 16
#define CS 128
#define GK 1024
#define NSUB 32   // sub-chunks per head (2 per chunk)

// ---------------- scratch (no allocations allowed) ----------------
__device__ float g_gate[T*D];
__device__ float g_qkv[T*3*D];
__device__ float g_Q[T*D];
__device__ float g_K[T*D];
__device__ float g_V[T*D];
__device__ float g_lkv[H*NSUB*DH*DH];
__device__ float g_lks[H*NSUB*DH];
__device__ float g_Spre[H*NC*DH*DH];
__device__ float g_zpre[H*NC*DH];

// fp16 activations and weights (single-rounded)
__device__ __half g_xa[T*D];          // fp16(x)
__device__ __half g_xna[T*D];         // fp16(ln(x))
__device__ __half g_aa[T*D];          // fp16(attn out)
__device__ __half g_qwh[3*D*D];
__device__ __half g_gwh[D*D];
__device__ __half g_pwh[D*D];

// ---------------- helpers ----------------
__device__ __forceinline__ uint32_t smem_u32(const void* p){
  uint32_t a;
  asm("{ .reg .u64 t; cvta.to.shared.u64 t, %1; cvt.u32.u64 %0, t; }" : "=r"(a) : "l"(p));
  return a;
}
__device__ __forceinline__ float elu1f(float x){ return x > 0.f ? x + 1.f : expf(x); }

__device__ __forceinline__ void ldsm_x4(uint32_t* r, uint32_t addr){
  asm volatile("ldmatrix.sync.aligned.m8n8.x4.shared.b16 {%0,%1,%2,%3}, [%4];"
    : "=r"(r[0]), "=r"(r[1]), "=r"(r[2]), "=r"(r[3]) : "r"(addr));
}
__device__ __forceinline__ void mma_f16(float* c, const uint32_t* a, const uint32_t* b){
  asm volatile(
    "mma.sync.aligned.m16n8k16.row.col.f32.f16.f16.f32 "
    "{%0,%1,%2,%3},{%4,%5,%6,%7},{%8,%9},{%0,%1,%2,%3};"
    : "+f"(c[0]), "+f"(c[1]), "+f"(c[2]), "+f"(c[3])
    : "r"(a[0]), "r"(a[1]), "r"(a[2]), "r"(a[3]), "r"(b[0]), "r"(b[1]));
}
__device__ __forceinline__ void cp16(uint32_t smem, const void* gmem){
  asm volatile("cp.async.cg.shared.global [%0], [%1], 16;" :: "r"(smem), "l"(gmem));
}
__device__ __forceinline__ void cp_commit(){
  asm volatile("cp.async.commit_group;" ::: "memory");
}
template<int N>
__device__ __forceinline__ void cp_wait(){
  asm volatile("cp.async.wait_group %0;" :: "n"(N) : "memory");
}

// ---------------- fused split(+LN) kernel ----------------
#define X4 (T*D/4)
#define Q4 (3*D*D/4)
#define G4 (D*D/4)
#define P4 (D*D/4)
#define NB_SPLIT ((X4 + Q4 + G4 + P4) / 256)
__global__ void split_ln_kernel(const float* __restrict__ x, const float* __restrict__ qw,
                                const float* __restrict__ gw, const float* __restrict__ pw,
                                const float* __restrict__ ln_g, const float* __restrict__ ln_b)
{
  if ((int)blockIdx.x < NB_SPLIT){
    int i = blockIdx.x * 256 + threadIdx.x;
    const float* src; __half* hp; int j;
    if (i < X4){ src = x; hp = g_xa; j = i; }
    else if (i < X4 + Q4){ src = qw; hp = g_qwh; j = i - X4; }
    else if (i < X4 + Q4 + G4){ src = gw; hp = g_gwh; j = i - (X4 + Q4); }
    else { src = pw; hp = g_pwh; j = i - (X4 + Q4 + G4); }
    float4 v = ((const float4*)src)[j];
    ((__half2*)hp)[j*2]   = __floats2half2_rn(v.x, v.y);
    ((__half2*)hp)[j*2+1] = __floats2half2_rn(v.z, v.w);
    return;
  }
  __shared__ float red[16];
  const int t = blockIdx.x - NB_SPLIT;
  const int i = threadIdx.x;
  float4 xv = ((const float4*)(x + (size_t)t*D))[i];
  float s  = xv.x + xv.y + xv.z + xv.w;
  float s2 = xv.x*xv.x + xv.y*xv.y + xv.z*xv.z + xv.w*xv.w;
  const int lane = i & 31, w = i >> 5;
  #pragma unroll
  for (int o = 16; o; o >>= 1){
    s  += __shfl_xor_sync(0xffffffffu, s,  o);
    s2 += __shfl_xor_sync(0xffffffffu, s2, o);
  }
  if (lane == 0){ red[w] = s; red[8+w] = s2; }
  __syncthreads();
  if (i == 0){
    float a = 0.f, c = 0.f;
    #pragma unroll
    for (int k = 0; k < 8; k++){ a += red[k]; c += red[8+k]; }
    red[0] = a; red[8] = c;
  }
  __syncthreads();
  const float mu   = red[0] * (1.f / D);
  const float var  = red[8] * (1.f / D) - mu * mu;
  const float rstd = rsqrtf(var + 1e-5f);
  float4 gv = ((const float4*)ln_g)[i];
  float4 bv = ((const float4*)ln_b)[i];
  float o0 = (xv.x - mu) * rstd * gv.x + bv.x;
  float o1 = (xv.y - mu) * rstd * gv.y + bv.y;
  float o2 = (xv.z - mu) * rstd * gv.z + bv.z;
  float o3 = (xv.w - mu) * rstd * gv.w + bv.w;
  const size_t idx4 = ((size_t)t*D >> 2) + i;
  ((__half2*)g_xna)[idx4*2]   = __floats2half2_rn(o0, o1);
  ((__half2*)g_xna)[idx4*2+1] = __floats2half2_rn(o2, o3);
}

// ---------------- HMMA GEMM: C[2048,N] = A[2048,1024] @ B[N,1024]^T ----------------
#define PITCH 80           // bytes per SMEM row (64B data + 16B pad)
#define ARR   (128*PITCH)  // 10240 B per array
#define STAGE (2*ARR)      // A + B = 20480 B
#define NRING 4
#define NKT   (GK/32)      // 32 k-tiles
#define GEMM_SMEM (NRING*STAGE)  // 81920 B

struct GArgs {
  const __half* A;
  const __half* B;
  const float* bias;
  float* C;
  int N;
  int sig;
};

__device__ __forceinline__ void gemm_load_stage(uint32_t sbase,
    const __half* A, const __half* B, int kt, int tid)
{
  const int koff = kt * 32;
  #pragma unroll
  for (int it = 0; it < 2; it++){
    const int w = tid + it * 256;      // 0..511
    const int row = w >> 2, c16 = w & 3;
    cp16(sbase + row*PITCH + c16*16,       A + (size_t)row * GK + koff + c16*8);
    cp16(sbase + ARR + row*PITCH + c16*16, B + (size_t)row * GK + koff + c16*8);
  }
}

__global__ void __launch_bounds__(256, 2)
hmma_gemm_dual(GArgs g0, GArgs g1, int split)
{
  extern __shared__ __align__(128) char sm[];
  const uint32_t sb = smem_u32(sm);
  const int tid = threadIdx.x;
  const int wid = tid >> 5, lane = tid & 31;
  const int wm = wid & 1, wn = wid >> 1;
  const int m0w = wm * 64, n0w = wn * 32;

  const bool first = ((int)blockIdx.x < split);
  const GArgs ga = first ? g0 : g1;
  const int bxn = first ? (int)blockIdx.x : (int)blockIdx.x - split;
  const int bn0 = bxn << 7, bm0 = blockIdx.y << 7;

  const __half* pA = ga.A + (size_t)bm0 * GK;
  const __half* pB = ga.B + (size_t)bn0 * GK;

  float acc[4][4][4];
  #pragma unroll
  for (int i = 0; i < 4; i++)
    #pragma unroll
    for (int j = 0; j < 4; j++)
      #pragma unroll
      for (int q = 0; q < 4; q++) acc[i][j][q] = 0.f;

  const int rowA = lane & 15;
  const uint32_t colA = (lane >> 4) << 4;
  const int rowB = (lane & 7) + (((lane >> 4) & 1) << 3);
  const uint32_t colB = ((lane >> 3) & 1) << 4;

  gemm_load_stage(sb + 0*STAGE, pA, pB, 0, tid); cp_commit();
  gemm_load_stage(sb + 1*STAGE, pA, pB, 1, tid); cp_commit();
  gemm_load_stage(sb + 2*STAGE, pA, pB, 2, tid); cp_commit();

  for (int kt = 0; kt < NKT; kt++){
    cp_wait<2>();
    __syncthreads();

    if (kt + 3 < NKT)
      gemm_load_stage(sb + ((kt + 3) & (NRING-1)) * STAGE, pA, pB, kt + 3, tid);
    cp_commit();

    const uint32_t st = sb + (kt & (NRING-1)) * STAGE;
    const uint32_t aB = st       + (m0w + rowA) * PITCH + colA;
    const uint32_t bB = st + ARR + (n0w + rowB) * PITCH + colB;

    #pragma unroll
    for (int ks = 0; ks < 2; ks++){
      const uint32_t kb = ks * 32;
      uint32_t a16[4][4], b16[4][2];
      #pragma unroll
      for (int mi = 0; mi < 4; mi++)
        ldsm_x4(a16[mi], aB + mi*16*PITCH + kb);
      #pragma unroll
      for (int p = 0; p < 2; p++){
        uint32_t r[4];
        ldsm_x4(r, bB + p*16*PITCH + kb);
        b16[2*p][0] = r[0]; b16[2*p][1] = r[1];
        b16[2*p+1][0] = r[2]; b16[2*p+1][1] = r[3];
      }
      #pragma unroll
      for (int mi = 0; mi < 4; mi++)
        #pragma unroll
        for (int nj = 0; nj < 4; nj++)
          mma_f16(acc[mi][nj], a16[mi], b16[nj]);
    }
  }

  const int g = lane >> 2, t4 = lane & 3;
  #pragma unroll
  for (int mi = 0; mi < 4; mi++){
    #pragma unroll
    for (int nj = 0; nj < 4; nj++){
      const int row = bm0 + m0w + mi*16 + g;
      const int col = bn0 + n0w + nj*8 + t4*2;
      float b0 = ga.bias[col], b1 = ga.bias[col+1];
      float o0 = acc[mi][nj][0] + b0;
      float o1 = acc[mi][nj][1] + b1;
      float o2 = acc[mi][nj][2] + b0;
      float o3 = acc[mi][nj][3] + b1;
      if (ga.sig){
        o0 = 1.f / (1.f + expf(-o0)); o1 = 1.f / (1.f + expf(-o1));
        o2 = 1.f / (1.f + expf(-o2)); o3 = 1.f / (1.f + expf(-o3));
      }
      *(float2*)(ga.C + (size_t)row * ga.N + col)       = make_float2(o0, o1);
      *(float2*)(ga.C + (size_t)(row + 8) * ga.N + col) = make_float2(o2, o3);
    }
  }
}

// ---------------- gate-normalize + apply + elu+1 + head split ----------------
__global__ void prep_kernel(const float* __restrict__ gate, const float* __restrict__ qkv,
                            float* __restrict__ Q, float* __restrict__ K, float* __restrict__ V)
{
  __shared__ float red[8];
  const int t = blockIdx.x, i = threadIdx.x;
  float4 gv = ((const float4*)(gate + (size_t)t*D))[i];
  float s = gv.x + gv.y + gv.z + gv.w;
  const int lane = i & 31, w = i >> 5;
  #pragma unroll
  for (int o = 16; o; o >>= 1) s += __shfl_xor_sync(0xffffffffu, s, o);
  if (lane == 0) red[w] = s;
  __syncthreads();
  if (i == 0){
    float a = 0.f;
    #pragma unroll
    for (int k = 0; k < 8; k++) a += red[k];
    red[0] = a;
  }
  __syncthreads();
  const float inv = 1.f / (red[0] * (1.f / D) + 1e-5f);

  const float4* qrow = (const float4*)(qkv + (size_t)t * 3 * D);
  float4 qv = qrow[i], kv = qrow[i + 256], vv = qrow[i + 512];
  float4 qo, ko;
  qo.x = elu1f(qv.x * gv.x * inv); qo.y = elu1f(qv.y * gv.y * inv);
  qo.z = elu1f(qv.z * gv.z * inv); qo.w = elu1f(qv.w * gv.w * inv);
  ko.x = elu1f(kv.x * gv.x * inv); ko.y = elu1f(kv.y * gv.y * inv);
  ko.z = elu1f(kv.z * gv.z * inv); ko.w = elu1f(kv.w * gv.w * inv);

  const int h = i >> 4;
  const int dh = (i & 15) << 2;
  const size_t b4 = ((size_t)(h * T + t) * DH + dh) >> 2;
  ((float4*)Q)[b4] = qo;
  ((float4*)K)[b4] = ko;
  ((float4*)V)[b4] = vv;
}

// ---------------- per-(head,sub-chunk) local K^T V and K column sums ----------------
// grid = H*NSUB (512 blocks), 64 rows per block
__global__ void chunk_sums_kernel(const float* __restrict__ Kg, const float* __restrict__ Vg,
                                  float* __restrict__ lkv, float* __restrict__ lks)
{
  extern __shared__ float smf[];
  float* Ks = smf;            // 64 x 64
  float* Vs = smf + 64 * DH;  // 64 x 64
  const int b = blockIdx.x;
  const int h = b >> 5, sub = b & 31;
  const int row0 = sub * 64;
  const float* Kc = Kg + ((size_t)h * T + row0) * DH;
  const float* Vc = Vg + ((size_t)h * T + row0) * DH;
  const int tid = threadIdx.x;
  #pragma unroll
  for (int it = 0; it < 4; it++){
    const int idx = tid + it * 256;   // 0..1023 float4s
    ((float4*)Ks)[idx] = ((const float4*)Kc)[idx];
    ((float4*)Vs)[idx] = ((const float4*)Vc)[idx];
  }
  __syncthreads();

  const int m = tid & 63;
  const int dg = tid >> 6;
  float acc[16];
  #pragma unroll
  for (int i = 0; i < 16; i++) acc[i] = 0.f;
  for (int tt = 0; tt < 64; tt++){
    const float vv = Vs[tt * DH + m];
    #pragma unroll
    for (int i = 0; i < 16; i++)
      acc[i] += Ks[tt * DH + dg * 16 + i] * vv;
  }
  float* dst = lkv + (size_t)b * DH * DH;
  #pragma unroll
  for (int i = 0; i < 16; i++)
    dst[(dg * 16 + i) * DH + m] = acc[i];

  if (tid < DH){
    float s = 0.f;
    for (int tt = 0; tt < 64; tt++) s += Ks[tt * DH + tid];
    lks[(size_t)b * DH + tid] = s;
  }
}

// ---------------- exclusive prefix over sub-chunks -> per-chunk Spre/zpre ----------------
// grid = dim3(16, H): block (e,h) owns elements [e*256, e*256+256) of the 4096
__global__ void scan_kernel(const float* __restrict__ lkv, const float* __restrict__ lks,
                            float* __restrict__ Spre, float* __restrict__ zpre)
{
  const int h = blockIdx.y;
  const int idx = blockIdx.x * 256 + threadIdx.x;   // 0..4095
  float acc = 0.f;
  #pragma unroll
  for (int s = 0; s < NSUB; s++){
    if (!(s & 1))
      Spre[((size_t)(h * NC + (s >> 1))) * DH * DH + idx] = acc;
    acc += lkv[((size_t)(h * NSUB + s)) * DH * DH + idx];
  }
  if (blockIdx.x == 0 && threadIdx.x < DH){
    const int d = threadIdx.x;
    float a = 0.f;
    #pragma unroll
    for (int s = 0; s < NSUB; s++){
      if (!(s & 1))
        zpre[(h * NC + (s >> 1)) * DH + d] = a;
      a += lks[(h * NSUB + s) * DH + d];
    }
  }
}

// ---------------- per-(head,chunk) attention output -> fp16 (512 threads) ----------------
__global__ void __launch_bounds__(512, 1)
attn_kernel(const float* __restrict__ Qg, const float* __restrict__ Kg,
            const float* __restrict__ Vg, const float* __restrict__ Spre,
            const float* __restrict__ zpre)
{
  extern __shared__ float smf[];
  float* Qs  = smf;              // 128 x 65
  float* Ks  = Qs  + 128 * 65;   // 128 x 65 (later reused for V)
  float* As  = Ks  + 128 * 65;   // 128 x 130
  float* Sp  = As  + 128 * 130;  // 64 x 65
  float* zp  = Sp  + 64 * 65;    // 64
  float* dn  = zp  + 64;         // 128
  float* dnp = dn  + 128;        // 128 x 16

  const int hc = blockIdx.x, h = hc >> 4, c = hc & 15;
  const int tid = threadIdx.x;
  const float* Qc = Qg + (size_t)(h * T + c * CS) * DH;
  const float* Kc = Kg + (size_t)(h * T + c * CS) * DH;

  for (int idx = tid; idx < CS * DH / 4; idx += 512){
    const int r = idx >> 4, c4 = (idx & 15) << 2;
    float4 q = ((const float4*)Qc)[idx];
    float4 k = ((const float4*)Kc)[idx];
    float* qd = Qs + r * 65 + c4;
    qd[0] = q.x; qd[1] = q.y; qd[2] = q.z; qd[3] = q.w;
    float* kd = Ks + r * 65 + c4;
    kd[0] = k.x; kd[1] = k.y; kd[2] = k.z; kd[3] = k.w;
  }
  const float* SpG = Spre + (size_t)hc * DH * DH;
  for (int idx = tid; idx < DH * DH; idx += 512)
    Sp[(idx >> 6) * 65 + (idx & 63)] = SpG[idx];
  if (tid < 64) zp[tid] = zpre[(size_t)hc * DH + tid];
  __syncthreads();

  if (tid < 128){
    float s = 0.f;
    #pragma unroll
    for (int d = 0; d < 64; d++) s += Qs[tid * 65 + d] * zp[d];
    dn[tid] = s;
  }
  __syncthreads();

  const int tx = tid & 15, ty = tid >> 4;   // tx 0..15, ty 0..31
  // phase 1: A = QK^T with causal mask; each thread 4 rows x 8 cols
  {
    float acc[4][8];
    #pragma unroll
    for (int i = 0; i < 4; i++)
      #pragma unroll
      for (int j = 0; j < 8; j++) acc[i][j] = 0.f;
    for (int d = 0; d < 64; d++){
      float a[4], b[8];
      #pragma unroll
      for (int i = 0; i < 4; i++) a[i] = Qs[(ty * 4 + i) * 65 + d];
      #pragma unroll
      for (int j = 0; j < 8; j++) b[j] = Ks[(tx * 8 + j) * 65 + d];
      #pragma unroll
      for (int i = 0; i < 4; i++)
        #pragma unroll
        for (int j = 0; j < 8; j++)
          acc[i][j] += a[i] * b[j];
    }
    #pragma unroll
    for (int i = 0; i < 4; i++){
      const int r = ty * 4 + i;
      float rs = 0.f;
      #pragma unroll
      for (int j = 0; j < 8; j++){
        const int s_ = tx * 8 + j;
        const float v = (s_ <= r) ? acc[i][j] : 0.f;
        As[r * 130 + s_] = v;
        rs += v;
      }
      dnp[r * 16 + tx] = rs;
    }
  }
  __syncthreads();

  // load V over K buffer; finalize den
  {
    const float* Vc = Vg + (size_t)(h * T + c * CS) * DH;
    for (int idx = tid; idx < CS * DH / 4; idx += 512){
      const int r = idx >> 4, c4 = (idx & 15) << 2;
      float4 v = ((const float4*)Vc)[idx];
      float* vd = Ks + r * 65 + c4;
      vd[0] = v.x; vd[1] = v.y; vd[2] = v.z; vd[3] = v.w;
    }
    if (tid < 128){
      float s = dn[tid];
      #pragma unroll
      for (int xx = 0; xx < 16; xx++) s += dnp[tid * 16 + xx];
      dn[tid] = s + 1e-5f;
    }
  }
  __syncthreads();

  // phase 2: out = (A@V + Q@Spre)/den; each thread 4 rows x 4 cols
  {
    float acc2[4][4];
    #pragma unroll
    for (int i = 0; i < 4; i++)
      #pragma unroll
      for (int j = 0; j < 4; j++) acc2[i][j] = 0.f;
    const int m0 = tx * 4, r0 = ty * 4;
    for (int s = 0; s < 128; s++){
      float vv[4];
      #pragma unroll
      for (int jj = 0; jj < 4; jj++) vv[jj] = Ks[s * 65 + m0 + jj];
      #pragma unroll
      for (int i = 0; i < 4; i++){
        const float av = As[(r0 + i) * 130 + s];
        #pragma unroll
        for (int jj = 0; jj < 4; jj++) acc2[i][jj] += av * vv[jj];
      }
    }
    for (int d = 0; d < 64; d++){
      float sp[4];
      #pragma unroll
      for (int jj = 0; jj < 4; jj++) sp[jj] = Sp[d * 65 + m0 + jj];
      #pragma unroll
      for (int i = 0; i < 4; i++){
        const float qv = Qs[(r0 + i) * 65 + d];
        #pragma unroll
        for (int jj = 0; jj < 4; jj++) acc2[i][jj] += qv * sp[jj];
      }
    }
    const size_t obase = (size_t)(c * CS) * D + h * DH;
    #pragma unroll
    for (int i = 0; i < 4; i++){
      const float inv = 1.f / dn[r0 + i];
      const size_t ptr = obase + (size_t)(r0 + i) * D + m0;
      *(__half2*)&g_aa[ptr]     = __floats2half2_rn(acc2[i][0] * inv, acc2[i][1] * inv);
      *(__half2*)&g_aa[ptr + 2] = __floats2half2_rn(acc2[i][2] * inv, acc2[i][3] * inv);
    }
  }
}

// ---------------- launch ----------------
extern "C" void kernel_launch(void* const* d_in, const int* in_sizes, int n_in,
                              void* d_out, int out_size)
{
  (void)in_sizes; (void)n_in; (void)out_size;
  const float* x      = (const float*)d_in[0];
  const float* ln_g   = (const float*)d_in[1];
  const float* ln_b   = (const float*)d_in[2];
  const float* qkv_w  = (const float*)d_in[3];
  const float* qkv_b  = (const float*)d_in[4];
  const float* gate_w = (const float*)d_in[5];
  const float* gate_b = (const float*)d_in[6];
  const float* proj_w = (const float*)d_in[7];
  const float* proj_b = (const float*)d_in[8];
  float* out = (float*)d_out;

  float *gate, *qkv, *Q, *K, *V, *lkv, *lks, *Spre, *zpre;
  __half *xa, *xna, *aa, *qwh, *gwh, *pwh;
  cudaGetSymbolAddress((void**)&gate, g_gate);
  cudaGetSymbolAddress((void**)&qkv,  g_qkv);
  cudaGetSymbolAddress((void**)&Q,    g_Q);
  cudaGetSymbolAddress((void**)&K,    g_K);
  cudaGetSymbolAddress((void**)&V,    g_V);
  cudaGetSymbolAddress((void**)&lkv,  g_lkv);
  cudaGetSymbolAddress((void**)&lks,  g_lks);
  cudaGetSymbolAddress((void**)&Spre, g_Spre);
  cudaGetSymbolAddress((void**)&zpre, g_zpre);
  cudaGetSymbolAddress((void**)&xa,   g_xa);
  cudaGetSymbolAddress((void**)&xna,  g_xna);
  cudaGetSymbolAddress((void**)&aa,   g_aa);
  cudaGetSymbolAddress((void**)&qwh,  g_qwh);
  cudaGetSymbolAddress((void**)&gwh,  g_gwh);
  cudaGetSymbolAddress((void**)&pwh,  g_pwh);

  const int CHUNK_SMEM = 2 * 64 * DH * 4;   // 32768
  const int ATTN_SMEM  = (128*65 + 128*65 + 128*130 + 64*65 + 64 + 128 + 128*16) * 4;
  cudaFuncSetAttribute(chunk_sums_kernel, cudaFuncAttributeMaxDynamicSharedMemorySize, CHUNK_SMEM);
  cudaFuncSetAttribute(attn_kernel,       cudaFuncAttributeMaxDynamicSharedMemorySize, ATTN_SMEM);
  cudaFuncSetAttribute(hmma_gemm_dual,    cudaFuncAttributeMaxDynamicSharedMemorySize, GEMM_SMEM);

  // fused conversions + LayerNorm
  split_ln_kernel<<<NB_SPLIT + T, 256>>>(x, qkv_w, gate_w, proj_w, ln_g, ln_b);

  // gate + qkv single-term fp16 (merged launch)
  GArgs gateArgs = { xa,  gwh, gate_b, gate, D,     1 };
  GArgs qkvArgs  = { xna, qwh, qkv_b,  qkv,  3 * D, 0 };
  hmma_gemm_dual<<<dim3(8 + 24, T / 128), 256, GEMM_SMEM>>>(gateArgs, qkvArgs, 8);

  prep_kernel<<<T, 256>>>(gate, qkv, Q, K, V);
  chunk_sums_kernel<<<H * NSUB, 256, CHUNK_SMEM>>>(K, V, lkv, lks);
  scan_kernel<<<dim3(16, H), 256>>>(lkv, lks, Spre, zpre);
  attn_kernel<<<H * NC, 512, ATTN_SMEM>>>(Q, K, V, Spre, zpre);

  // proj: single-term fp16
  GArgs projArgs = { aa, pwh, proj_b, out, D, 0 };
  hmma_gemm_dual<<<dim3(8, T / 128), 256, GEMM_SMEM>>>(projArgs, projArgs, 8);
}

// round 11
// speedup vs baseline: 2.3004x; 1.0991x over previous
#include <cuda_runtime.h>
#include <cuda_fp16.h>
#include <cstdint>
#include <math.h>

#define T 2048
#define D 1024
#define H 16
#define DH 64
#define NC 16
#define CS 128
#define GK 1024
#define NSUB 32   // sub-chunks per head (2 per chunk)

// ---------------- scratch (no allocations allowed) ----------------
__device__ float g_gate[T*D];
__device__ float g_qkv[T*3*D];
__device__ float g_Q[T*D];
__device__ float g_K[T*D];
__device__ float g_V[T*D];
__device__ float g_lkv[H*NSUB*DH*DH];
__device__ float g_lks[H*NSUB*DH];
__device__ float g_Spre[H*NC*DH*DH];
__device__ float g_zpre[H*NC*DH];

// fp16 activations and weights (single-rounded)
__device__ __half g_xa[T*D];          // fp16(x)
__device__ __half g_xna[T*D];         // fp16(ln(x))
__device__ __half g_aa[T*D];          // fp16(attn out)
__device__ __half g_qwh[3*D*D];
__device__ __half g_gwh[D*D];
__device__ __half g_pwh[D*D];

// ---------------- helpers ----------------
__device__ __forceinline__ uint32_t smem_u32(const void* p){
  uint32_t a;
  asm("{ .reg .u64 t; cvta.to.shared.u64 t, %1; cvt.u32.u64 %0, t; }" : "=r"(a) : "l"(p));
  return a;
}
__device__ __forceinline__ float elu1f(float x){ return x > 0.f ? x + 1.f : expf(x); }

__device__ __forceinline__ void ldsm_x4(uint32_t* r, uint32_t addr){
  asm volatile("ldmatrix.sync.aligned.m8n8.x4.shared.b16 {%0,%1,%2,%3}, [%4];"
    : "=r"(r[0]), "=r"(r[1]), "=r"(r[2]), "=r"(r[3]) : "r"(addr));
}
__device__ __forceinline__ void mma_f16(float* c, const uint32_t* a, const uint32_t* b){
  asm volatile(
    "mma.sync.aligned.m16n8k16.row.col.f32.f16.f16.f32 "
    "{%0,%1,%2,%3},{%4,%5,%6,%7},{%8,%9},{%0,%1,%2,%3};"
    : "+f"(c[0]), "+f"(c[1]), "+f"(c[2]), "+f"(c[3])
    : "r"(a[0]), "r"(a[1]), "r"(a[2]), "r"(a[3]), "r"(b[0]), "r"(b[1]));
}
__device__ __forceinline__ void cp16(uint32_t smem, const void* gmem){
  asm volatile("cp.async.cg.shared.global [%0], [%1], 16;" :: "r"(smem), "l"(gmem));
}
__device__ __forceinline__ void cp_commit(){
  asm volatile("cp.async.commit_group;" ::: "memory");
}
template<int N>
__device__ __forceinline__ void cp_wait(){
  asm volatile("cp.async.wait_group %0;" :: "n"(N) : "memory");
}

// ---------------- fused split(+LN) kernel ----------------
#define X4 (T*D/4)
#define Q4 (3*D*D/4)
#define G4 (D*D/4)
#define P4 (D*D/4)
#define NB_SPLIT ((X4 + Q4 + G4 + P4) / 256)
__global__ void split_ln_kernel(const float* __restrict__ x, const float* __restrict__ qw,
                                const float* __restrict__ gw, const float* __restrict__ pw,
                                const float* __restrict__ ln_g, const float* __restrict__ ln_b)
{
  if ((int)blockIdx.x < NB_SPLIT){
    int i = blockIdx.x * 256 + threadIdx.x;
    const float* src; __half* hp; int j;
    if (i < X4){ src = x; hp = g_xa; j = i; }
    else if (i < X4 + Q4){ src = qw; hp = g_qwh; j = i - X4; }
    else if (i < X4 + Q4 + G4){ src = gw; hp = g_gwh; j = i - (X4 + Q4); }
    else { src = pw; hp = g_pwh; j = i - (X4 + Q4 + G4); }
    float4 v = ((const float4*)src)[j];
    ((__half2*)hp)[j*2]   = __floats2half2_rn(v.x, v.y);
    ((__half2*)hp)[j*2+1] = __floats2half2_rn(v.z, v.w);
    return;
  }
  __shared__ float red[16];
  const int t = blockIdx.x - NB_SPLIT;
  const int i = threadIdx.x;
  float4 xv = ((const float4*)(x + (size_t)t*D))[i];
  float s  = xv.x + xv.y + xv.z + xv.w;
  float s2 = xv.x*xv.x + xv.y*xv.y + xv.z*xv.z + xv.w*xv.w;
  const int lane = i & 31, w = i >> 5;
  #pragma unroll
  for (int o = 16; o; o >>= 1){
    s  += __shfl_xor_sync(0xffffffffu, s,  o);
    s2 += __shfl_xor_sync(0xffffffffu, s2, o);
  }
  if (lane == 0){ red[w] = s; red[8+w] = s2; }
  __syncthreads();
  if (i == 0){
    float a = 0.f, c = 0.f;
    #pragma unroll
    for (int k = 0; k < 8; k++){ a += red[k]; c += red[8+k]; }
    red[0] = a; red[8] = c;
  }
  __syncthreads();
  const float mu   = red[0] * (1.f / D);
  const float var  = red[8] * (1.f / D) - mu * mu;
  const float rstd = rsqrtf(var + 1e-5f);
  float4 gv = ((const float4*)ln_g)[i];
  float4 bv = ((const float4*)ln_b)[i];
  float o0 = (xv.x - mu) * rstd * gv.x + bv.x;
  float o1 = (xv.y - mu) * rstd * gv.y + bv.y;
  float o2 = (xv.z - mu) * rstd * gv.z + bv.z;
  float o3 = (xv.w - mu) * rstd * gv.w + bv.w;
  const size_t idx4 = ((size_t)t*D >> 2) + i;
  ((__half2*)g_xna)[idx4*2]   = __floats2half2_rn(o0, o1);
  ((__half2*)g_xna)[idx4*2+1] = __floats2half2_rn(o2, o3);
}

// ---------------- HMMA GEMM: C[2048,N] = A[2048,1024] @ B[N,1024]^T ----------------
#define PITCH 80           // bytes per SMEM row (64B data + 16B pad)
#define ARR   (128*PITCH)  // 10240 B per array
#define STAGE (2*ARR)      // A + B = 20480 B
#define NRING 4
#define NKT   (GK/32)      // 32 k-tiles
#define GEMM_SMEM (NRING*STAGE)  // 81920 B

struct GArgs {
  const __half* A;
  const __half* B;
  const float* bias;
  float* C;
  int N;
  int sig;
};

__device__ __forceinline__ void gemm_load_stage(uint32_t sbase,
    const __half* A, const __half* B, int kt, int tid)
{
  const int koff = kt * 32;
  #pragma unroll
  for (int it = 0; it < 2; it++){
    const int w = tid + it * 256;      // 0..511
    const int row = w >> 2, c16 = w & 3;
    cp16(sbase + row*PITCH + c16*16,       A + (size_t)row * GK + koff + c16*8);
    cp16(sbase + ARR + row*PITCH + c16*16, B + (size_t)row * GK + koff + c16*8);
  }
}

__global__ void __launch_bounds__(256, 2)
hmma_gemm_dual(GArgs g0, GArgs g1, int split)
{
  extern __shared__ __align__(128) char sm[];
  const uint32_t sb = smem_u32(sm);
  const int tid = threadIdx.x;
  const int wid = tid >> 5, lane = tid & 31;
  const int wm = wid & 1, wn = wid >> 1;
  const int m0w = wm * 64, n0w = wn * 32;

  const bool first = ((int)blockIdx.x < split);
  const GArgs ga = first ? g0 : g1;
  const int bxn = first ? (int)blockIdx.x : (int)blockIdx.x - split;
  const int bn0 = bxn << 7, bm0 = blockIdx.y << 7;

  const __half* pA = ga.A + (size_t)bm0 * GK;
  const __half* pB = ga.B + (size_t)bn0 * GK;

  float acc[4][4][4];
  #pragma unroll
  for (int i = 0; i < 4; i++)
    #pragma unroll
    for (int j = 0; j < 4; j++)
      #pragma unroll
      for (int q = 0; q < 4; q++) acc[i][j][q] = 0.f;

  const int rowA = lane & 15;
  const uint32_t colA = (lane >> 4) << 4;
  const int rowB = (lane & 7) + (((lane >> 4) & 1) << 3);
  const uint32_t colB = ((lane >> 3) & 1) << 4;

  gemm_load_stage(sb + 0*STAGE, pA, pB, 0, tid); cp_commit();
  gemm_load_stage(sb + 1*STAGE, pA, pB, 1, tid); cp_commit();
  gemm_load_stage(sb + 2*STAGE, pA, pB, 2, tid); cp_commit();

  for (int kt = 0; kt < NKT; kt++){
    cp_wait<2>();
    __syncthreads();

    if (kt + 3 < NKT)
      gemm_load_stage(sb + ((kt + 3) & (NRING-1)) * STAGE, pA, pB, kt + 3, tid);
    cp_commit();

    const uint32_t st = sb + (kt & (NRING-1)) * STAGE;
    const uint32_t aB = st       + (m0w + rowA) * PITCH + colA;
    const uint32_t bB = st + ARR + (n0w + rowB) * PITCH + colB;

    #pragma unroll
    for (int ks = 0; ks < 2; ks++){
      const uint32_t kb = ks * 32;
      uint32_t a16[4][4], b16[4][2];
      #pragma unroll
      for (int mi = 0; mi < 4; mi++)
        ldsm_x4(a16[mi], aB + mi*16*PITCH + kb);
      #pragma unroll
      for (int p = 0; p < 2; p++){
        uint32_t r[4];
        ldsm_x4(r, bB + p*16*PITCH + kb);
        b16[2*p][0] = r[0]; b16[2*p][1] = r[1];
        b16[2*p+1][0] = r[2]; b16[2*p+1][1] = r[3];
      }
      #pragma unroll
      for (int mi = 0; mi < 4; mi++)
        #pragma unroll
        for (int nj = 0; nj < 4; nj++)
          mma_f16(acc[mi][nj], a16[mi], b16[nj]);
    }
  }

  const int g = lane >> 2, t4 = lane & 3;
  #pragma unroll
  for (int mi = 0; mi < 4; mi++){
    #pragma unroll
    for (int nj = 0; nj < 4; nj++){
      const int row = bm0 + m0w + mi*16 + g;
      const int col = bn0 + n0w + nj*8 + t4*2;
      float b0 = ga.bias[col], b1 = ga.bias[col+1];
      float o0 = acc[mi][nj][0] + b0;
      float o1 = acc[mi][nj][1] + b1;
      float o2 = acc[mi][nj][2] + b0;
      float o3 = acc[mi][nj][3] + b1;
      if (ga.sig){
        o0 = 1.f / (1.f + expf(-o0)); o1 = 1.f / (1.f + expf(-o1));
        o2 = 1.f / (1.f + expf(-o2)); o3 = 1.f / (1.f + expf(-o3));
      }
      *(float2*)(ga.C + (size_t)row * ga.N + col)       = make_float2(o0, o1);
      *(float2*)(ga.C + (size_t)(row + 8) * ga.N + col) = make_float2(o2, o3);
    }
  }
}

// ---------------- gate-normalize + apply + elu+1 + head split ----------------
__global__ void prep_kernel(const float* __restrict__ gate, const float* __restrict__ qkv,
                            float* __restrict__ Q, float* __restrict__ K, float* __restrict__ V)
{
  __shared__ float red[8];
  const int t = blockIdx.x, i = threadIdx.x;
  float4 gv = ((const float4*)(gate + (size_t)t*D))[i];
  float s = gv.x + gv.y + gv.z + gv.w;
  const int lane = i & 31, w = i >> 5;
  #pragma unroll
  for (int o = 16; o; o >>= 1) s += __shfl_xor_sync(0xffffffffu, s, o);
  if (lane == 0) red[w] = s;
  __syncthreads();
  if (i == 0){
    float a = 0.f;
    #pragma unroll
    for (int k = 0; k < 8; k++) a += red[k];
    red[0] = a;
  }
  __syncthreads();
  const float inv = 1.f / (red[0] * (1.f / D) + 1e-5f);

  const float4* qrow = (const float4*)(qkv + (size_t)t * 3 * D);
  float4 qv = qrow[i], kv = qrow[i + 256], vv = qrow[i + 512];
  float4 qo, ko;
  qo.x = elu1f(qv.x * gv.x * inv); qo.y = elu1f(qv.y * gv.y * inv);
  qo.z = elu1f(qv.z * gv.z * inv); qo.w = elu1f(qv.w * gv.w * inv);
  ko.x = elu1f(kv.x * gv.x * inv); ko.y = elu1f(kv.y * gv.y * inv);
  ko.z = elu1f(kv.z * gv.z * inv); ko.w = elu1f(kv.w * gv.w * inv);

  const int h = i >> 4;
  const int dh = (i & 15) << 2;
  const size_t b4 = ((size_t)(h * T + t) * DH + dh) >> 2;
  ((float4*)Q)[b4] = qo;
  ((float4*)K)[b4] = ko;
  ((float4*)V)[b4] = vv;
}

// ---------------- per-(head,sub-chunk) local K^T V and K column sums ----------------
// grid = H*NSUB (512 blocks), 64 rows per block; 4x4 register tiles, float4 LDS
__global__ void chunk_sums_kernel(const float* __restrict__ Kg, const float* __restrict__ Vg,
                                  float* __restrict__ lkv, float* __restrict__ lks)
{
  extern __shared__ float smf[];
  float* Ks = smf;            // 64 x 64
  float* Vs = smf + 64 * DH;  // 64 x 64
  const int b = blockIdx.x;
  const int h = b >> 5, sub = b & 31;
  const int row0 = sub * 64;
  const float* Kc = Kg + ((size_t)h * T + row0) * DH;
  const float* Vc = Vg + ((size_t)h * T + row0) * DH;
  const int tid = threadIdx.x;
  #pragma unroll
  for (int it = 0; it < 4; it++){
    const int idx = tid + it * 256;   // 0..1023 float4s
    ((float4*)Ks)[idx] = ((const float4*)Kc)[idx];
    ((float4*)Vs)[idx] = ((const float4*)Vc)[idx];
  }
  __syncthreads();

  // thread (tm, td): 4 d-rows x 4 m-cols tile of the 64x64 K^T V
  const int tm = tid & 15, td = tid >> 4;
  const int m0 = tm * 4, d0 = td * 4;
  float acc[4][4];
  #pragma unroll
  for (int i = 0; i < 4; i++)
    #pragma unroll
    for (int j = 0; j < 4; j++) acc[i][j] = 0.f;
  for (int tt = 0; tt < 64; tt++){
    float4 k4 = *(const float4*)&Ks[tt * DH + d0];
    float4 v4 = *(const float4*)&Vs[tt * DH + m0];
    float kk[4] = {k4.x, k4.y, k4.z, k4.w};
    float vv[4] = {v4.x, v4.y, v4.z, v4.w};
    #pragma unroll
    for (int i = 0; i < 4; i++)
      #pragma unroll
      for (int j = 0; j < 4; j++)
        acc[i][j] += kk[i] * vv[j];
  }
  float* dst = lkv + (size_t)b * DH * DH;
  #pragma unroll
  for (int i = 0; i < 4; i++)
    *(float4*)&dst[(d0 + i) * DH + m0] = make_float4(acc[i][0], acc[i][1], acc[i][2], acc[i][3]);

  if (tid < DH){
    float s = 0.f;
    for (int tt = 0; tt < 64; tt++) s += Ks[tt * DH + tid];
    lks[(size_t)b * DH + tid] = s;
  }
}

// ---------------- exclusive prefix over sub-chunks -> per-chunk Spre/zpre ----------------
__global__ void scan_kernel(const float* __restrict__ lkv, const float* __restrict__ lks,
                            float* __restrict__ Spre, float* __restrict__ zpre)
{
  const int h = blockIdx.y;
  const int idx = blockIdx.x * 256 + threadIdx.x;   // 0..4095
  float acc = 0.f;
  #pragma unroll
  for (int s = 0; s < NSUB; s++){
    if (!(s & 1))
      Spre[((size_t)(h * NC + (s >> 1))) * DH * DH + idx] = acc;
    acc += lkv[((size_t)(h * NSUB + s)) * DH * DH + idx];
  }
  if (blockIdx.x == 0 && threadIdx.x < DH){
    const int d = threadIdx.x;
    float a = 0.f;
    #pragma unroll
    for (int s = 0; s < NSUB; s++){
      if (!(s & 1))
        zpre[(h * NC + (s >> 1)) * DH + d] = a;
      a += lks[(h * NSUB + s) * DH + d];
    }
  }
}

// ---------------- per-(head,chunk) attention output -> fp16 (512 threads) ----------------
__global__ void __launch_bounds__(512, 1)
attn_kernel(const float* __restrict__ Qg, const float* __restrict__ Kg,
            const float* __restrict__ Vg, const float* __restrict__ Spre,
            const float* __restrict__ zpre)
{
  extern __shared__ float smf[];
  float* Qs  = smf;              // 128 x 65
  float* Ks  = Qs  + 128 * 65;   // 128 x 65 (later reused for V)
  float* As  = Ks  + 128 * 65;   // 128 x 130
  float* Sp  = As  + 128 * 130;  // 64 x 65
  float* zp  = Sp  + 64 * 65;    // 64
  float* dn  = zp  + 64;         // 128
  float* dnp = dn  + 128;        // 128 x 16

  const int hc = blockIdx.x, h = hc >> 4, c = hc & 15;
  const int tid = threadIdx.x;
  const float* Qc = Qg + (size_t)(h * T + c * CS) * DH;
  const float* Kc = Kg + (size_t)(h * T + c * CS) * DH;

  for (int idx = tid; idx < CS * DH / 4; idx += 512){
    const int r = idx >> 4, c4 = (idx & 15) << 2;
    float4 q = ((const float4*)Qc)[idx];
    float4 k = ((const float4*)Kc)[idx];
    float* qd = Qs + r * 65 + c4;
    qd[0] = q.x; qd[1] = q.y; qd[2] = q.z; qd[3] = q.w;
    float* kd = Ks + r * 65 + c4;
    kd[0] = k.x; kd[1] = k.y; kd[2] = k.z; kd[3] = k.w;
  }
  const float* SpG = Spre + (size_t)hc * DH * DH;
  for (int idx = tid; idx < DH * DH; idx += 512)
    Sp[(idx >> 6) * 65 + (idx & 63)] = SpG[idx];
  if (tid < 64) zp[tid] = zpre[(size_t)hc * DH + tid];
  __syncthreads();

  if (tid < 128){
    float s = 0.f;
    #pragma unroll
    for (int d = 0; d < 64; d++) s += Qs[tid * 65 + d] * zp[d];
    dn[tid] = s;
  }
  __syncthreads();

  const int tx = tid & 15, ty = tid >> 4;   // tx 0..15, ty 0..31
  // phase 1: A = QK^T with causal mask; each thread 4 rows x 8 cols.
  // Tiles entirely above the diagonal (tx*8 > ty*4+3) skip all work
  // (their As region is never read by phase 2; dnp contribution is 0).
  {
    const int r_hi = ty * 4 + 3;
    if (tx * 8 <= r_hi){
      float acc[4][8];
      #pragma unroll
      for (int i = 0; i < 4; i++)
        #pragma unroll
        for (int j = 0; j < 8; j++) acc[i][j] = 0.f;
      for (int d = 0; d < 64; d++){
        float a[4], b[8];
        #pragma unroll
        for (int i = 0; i < 4; i++) a[i] = Qs[(ty * 4 + i) * 65 + d];
        #pragma unroll
        for (int j = 0; j < 8; j++) b[j] = Ks[(tx * 8 + j) * 65 + d];
        #pragma unroll
        for (int i = 0; i < 4; i++)
          #pragma unroll
          for (int j = 0; j < 8; j++)
            acc[i][j] += a[i] * b[j];
      }
      #pragma unroll
      for (int i = 0; i < 4; i++){
        const int r = ty * 4 + i;
        float rs = 0.f;
        #pragma unroll
        for (int j = 0; j < 8; j++){
          const int s_ = tx * 8 + j;
          const float v = (s_ <= r) ? acc[i][j] : 0.f;
          As[r * 130 + s_] = v;
          rs += v;
        }
        dnp[r * 16 + tx] = rs;
      }
    } else {
      #pragma unroll
      for (int i = 0; i < 4; i++)
        dnp[(ty * 4 + i) * 16 + tx] = 0.f;
    }
  }
  __syncthreads();

  // load V over K buffer; finalize den
  {
    const float* Vc = Vg + (size_t)(h * T + c * CS) * DH;
    for (int idx = tid; idx < CS * DH / 4; idx += 512){
      const int r = idx >> 4, c4 = (idx & 15) << 2;
      float4 v = ((const float4*)Vc)[idx];
      float* vd = Ks + r * 65 + c4;
      vd[0] = v.x; vd[1] = v.y; vd[2] = v.z; vd[3] = v.w;
    }
    if (tid < 128){
      float s = dn[tid];
      #pragma unroll
      for (int xx = 0; xx < 16; xx++) s += dnp[tid * 16 + xx];
      dn[tid] = s + 1e-5f;
    }
  }
  __syncthreads();

  // phase 2: out = (A@V + Q@Spre)/den; each thread 4 rows x 4 cols.
  // A@V only needs s <= row; rows in this tile max at r0+3 -> bound r0+4.
  {
    float acc2[4][4];
    #pragma unroll
    for (int i = 0; i < 4; i++)
      #pragma unroll
      for (int j = 0; j < 4; j++) acc2[i][j] = 0.f;
    const int m0 = tx * 4, r0 = ty * 4;
    const int send = r0 + 4;
    for (int s = 0; s < send; s++){
      float vv[4];
      #pragma unroll
      for (int jj = 0; jj < 4; jj++) vv[jj] = Ks[s * 65 + m0 + jj];
      #pragma unroll
      for (int i = 0; i < 4; i++){
        const float av = As[(r0 + i) * 130 + s];
        #pragma unroll
        for (int jj = 0; jj < 4; jj++) acc2[i][jj] += av * vv[jj];
      }
    }
    for (int d = 0; d < 64; d++){
      float sp[4];
      #pragma unroll
      for (int jj = 0; jj < 4; jj++) sp[jj] = Sp[d * 65 + m0 + jj];
      #pragma unroll
      for (int i = 0; i < 4; i++){
        const float qv = Qs[(r0 + i) * 65 + d];
        #pragma unroll
        for (int jj = 0; jj < 4; jj++) acc2[i][jj] += qv * sp[jj];
      }
    }
    const size_t obase = (size_t)(c * CS) * D + h * DH;
    #pragma unroll
    for (int i = 0; i < 4; i++){
      const float inv = 1.f / dn[r0 + i];
      const size_t ptr = obase + (size_t)(r0 + i) * D + m0;
      *(__half2*)&g_aa[ptr]     = __floats2half2_rn(acc2[i][0] * inv, acc2[i][1] * inv);
      *(__half2*)&g_aa[ptr + 2] = __floats2half2_rn(acc2[i][2] * inv, acc2[i][3] * inv);
    }
  }
}

// ---------------- launch ----------------
extern "C" void kernel_launch(void* const* d_in, const int* in_sizes, int n_in,
                              void* d_out, int out_size)
{
  (void)in_sizes; (void)n_in; (void)out_size;
  const float* x      = (const float*)d_in[0];
  const float* ln_g   = (const float*)d_in[1];
  const float* ln_b   = (const float*)d_in[2];
  const float* qkv_w  = (const float*)d_in[3];
  const float* qkv_b  = (const float*)d_in[4];
  const float* gate_w = (const float*)d_in[5];
  const float* gate_b = (const float*)d_in[6];
  const float* proj_w = (const float*)d_in[7];
  const float* proj_b = (const float*)d_in[8];
  float* out = (float*)d_out;

  float *gate, *qkv, *Q, *K, *V, *lkv, *lks, *Spre, *zpre;
  __half *xa, *xna, *aa, *qwh, *gwh, *pwh;
  cudaGetSymbolAddress((void**)&gate, g_gate);
  cudaGetSymbolAddress((void**)&qkv,  g_qkv);
  cudaGetSymbolAddress((void**)&Q,    g_Q);
  cudaGetSymbolAddress((void**)&K,    g_K);
  cudaGetSymbolAddress((void**)&V,    g_V);
  cudaGetSymbolAddress((void**)&lkv,  g_lkv);
  cudaGetSymbolAddress((void**)&lks,  g_lks);
  cudaGetSymbolAddress((void**)&Spre, g_Spre);
  cudaGetSymbolAddress((void**)&zpre, g_zpre);
  cudaGetSymbolAddress((void**)&xa,   g_xa);
  cudaGetSymbolAddress((void**)&xna,  g_xna);
  cudaGetSymbolAddress((void**)&aa,   g_aa);
  cudaGetSymbolAddress((void**)&qwh,  g_qwh);
  cudaGetSymbolAddress((void**)&gwh,  g_gwh);
  cudaGetSymbolAddress((void**)&pwh,  g_pwh);

  const int CHUNK_SMEM = 2 * 64 * DH * 4;   // 32768
  const int ATTN_SMEM  = (128*65 + 128*65 + 128*130 + 64*65 + 64 + 128 + 128*16) * 4;
  cudaFuncSetAttribute(chunk_sums_kernel, cudaFuncAttributeMaxDynamicSharedMemorySize, CHUNK_SMEM);
  cudaFuncSetAttribute(attn_kernel,       cudaFuncAttributeMaxDynamicSharedMemorySize, ATTN_SMEM);
  cudaFuncSetAttribute(hmma_gemm_dual,    cudaFuncAttributeMaxDynamicSharedMemorySize, GEMM_SMEM);

  // fused conversions + LayerNorm
  split_ln_kernel<<<NB_SPLIT + T, 256>>>(x, qkv_w, gate_w, proj_w, ln_g, ln_b);

  // gate + qkv single-term fp16 (merged launch)
  GArgs gateArgs = { xa,  gwh, gate_b, gate, D,     1 };
  GArgs qkvArgs  = { xna, qwh, qkv_b,  qkv,  3 * D, 0 };
  hmma_gemm_dual<<<dim3(8 + 24, T / 128), 256, GEMM_SMEM>>>(gateArgs, qkvArgs, 8);

  prep_kernel<<<T, 256>>>(gate, qkv, Q, K, V);
  chunk_sums_kernel<<<H * NSUB, 256, CHUNK_SMEM>>>(K, V, lkv, lks);
  scan_kernel<<<dim3(16, H), 256>>>(lkv, lks, Spre, zpre);
  attn_kernel<<<H * NC, 512, ATTN_SMEM>>>(Q, K, V, Spre, zpre);

  // proj: single-term fp16
  GArgs projArgs = { aa, pwh, proj_b, out, D, 0 };
  hmma_gemm_dual<<<dim3(8, T / 128), 256, GEMM_SMEM>>>(projArgs, projArgs, 8);
}